// round 2
// baseline (speedup 1.0000x reference)
#include <cuda_runtime.h>
#include <cuda_bf16.h>
#include <math.h>

// Problem constants
#define BATCH 16
#define CDIM 256
#define NDIM 4096          // 64*64 spatial
#define HEADS 4
#define ADIM 32
#define HID 128            // HEADS*ADIM
#define QKVROWS 384        // 3*HID
#define NMEM 4
#define SCALE 0.17677669529663687f   // 32^-0.5
#define EPSN 1e-12f

// Scratch (device globals: allocation-free per harness rules)
__device__ float g_rnorm[BATCH * NDIM];                 // 16*sqrt? -> 16/max(||x||,eps)
__device__ float g_qkv[(size_t)BATCH * QKVROWS * NDIM]; // ~100MB
__device__ float g_kmax[BATCH * HEADS * ADIM];
__device__ float g_ctx[BATCH * HEADS * ADIM * ADIM];    // already * SCALE / Z

// ---------------------------------------------------------------------------
// K1: per-(b,n) inverse channel norm: 16 / max(||x[:,n]||, eps)
// ---------------------------------------------------------------------------
__global__ __launch_bounds__(256) void k_rnorm(const float* __restrict__ x) {
    int idx = blockIdx.x * 256 + threadIdx.x;   // b*NDIM + n
    int b = idx >> 12;
    int n = idx & (NDIM - 1);
    const float* xp = x + (size_t)b * CDIM * NDIM + n;
    float s = 0.f;
    #pragma unroll 8
    for (int c = 0; c < CDIM; c++) {
        float v = xp[(size_t)c * NDIM];
        s += v * v;
    }
    g_rnorm[idx] = 16.0f / fmaxf(sqrtf(s), EPSN);
}

// ---------------------------------------------------------------------------
// K2: qkv[b,o,n] = sum_k (Wqkv[o,k]*g[k]) * x[b,k,n] * rnorm[b,n]
// Classic SGEMM: 128x128 block tile, BK=16, 8x8 per thread.
// ---------------------------------------------------------------------------
#define BM 128
#define BN 128
#define BK 16
__global__ __launch_bounds__(256) void k_qkv(const float* __restrict__ x,
                                             const float* __restrict__ wqkv,
                                             const float* __restrict__ gch) {
    __shared__ float As[BK][BM];
    __shared__ float Bs[BK][BN];
    int b  = blockIdx.z;
    int m0 = blockIdx.x * BM;
    int n0 = blockIdx.y * BN;
    int tid = threadIdx.x;
    int tx = tid & 15, ty = tid >> 4;

    const float* xb = x + (size_t)b * CDIM * NDIM;
    float acc[8][8];
    #pragma unroll
    for (int i = 0; i < 8; i++)
        #pragma unroll
        for (int j = 0; j < 8; j++) acc[i][j] = 0.f;

    for (int k0 = 0; k0 < CDIM; k0 += BK) {
        // A tile: 128 rows x 16 k, transposed into As[k][m], scaled by g[k]
        #pragma unroll
        for (int f = tid; f < 512; f += 256) {
            int row = f >> 2, c4 = f & 3;
            float4 v = *(const float4*)(wqkv + (size_t)(m0 + row) * CDIM + k0 + c4 * 4);
            int kk = c4 * 4;
            As[kk + 0][row] = v.x * gch[k0 + kk + 0];
            As[kk + 1][row] = v.y * gch[k0 + kk + 1];
            As[kk + 2][row] = v.z * gch[k0 + kk + 2];
            As[kk + 3][row] = v.w * gch[k0 + kk + 3];
        }
        // B tile: 16 k rows x 128 n
        #pragma unroll
        for (int f = tid; f < 512; f += 256) {
            int row = f >> 5, c4 = f & 31;
            float4 v = *(const float4*)(xb + (size_t)(k0 + row) * NDIM + n0 + c4 * 4);
            *(float4*)&Bs[row][c4 * 4] = v;
        }
        __syncthreads();
        #pragma unroll
        for (int kk = 0; kk < BK; kk++) {
            float a[8], bb[8];
            float4 a0 = *(const float4*)&As[kk][ty * 8];
            float4 a1 = *(const float4*)&As[kk][ty * 8 + 4];
            a[0]=a0.x; a[1]=a0.y; a[2]=a0.z; a[3]=a0.w;
            a[4]=a1.x; a[5]=a1.y; a[6]=a1.z; a[7]=a1.w;
            float4 b0 = *(const float4*)&Bs[kk][tx * 8];
            float4 b1 = *(const float4*)&Bs[kk][tx * 8 + 4];
            bb[0]=b0.x; bb[1]=b0.y; bb[2]=b0.z; bb[3]=b0.w;
            bb[4]=b1.x; bb[5]=b1.y; bb[6]=b1.z; bb[7]=b1.w;
            #pragma unroll
            for (int i = 0; i < 8; i++)
                #pragma unroll
                for (int j = 0; j < 8; j++) acc[i][j] += a[i] * bb[j];
        }
        __syncthreads();
    }
    // epilogue: scale by rnorm[n], write
    float rn[8];
    #pragma unroll
    for (int j = 0; j < 8; j++) rn[j] = g_rnorm[b * NDIM + n0 + tx * 8 + j];
    float* outp = g_qkv + (size_t)b * QKVROWS * NDIM;
    #pragma unroll
    for (int i = 0; i < 8; i++) {
        int o = m0 + ty * 8 + i;
        float4 v0 = make_float4(acc[i][0]*rn[0], acc[i][1]*rn[1], acc[i][2]*rn[2], acc[i][3]*rn[3]);
        float4 v1 = make_float4(acc[i][4]*rn[4], acc[i][5]*rn[5], acc[i][6]*rn[6], acc[i][7]*rn[7]);
        *(float4*)(outp + (size_t)o * NDIM + n0 + tx * 8)     = v0;
        *(float4*)(outp + (size_t)o * NDIM + n0 + tx * 8 + 4) = v1;
    }
}

// ---------------------------------------------------------------------------
// K3a: per-(b,h,d) max over n (including 4 memory tokens)
// ---------------------------------------------------------------------------
__global__ __launch_bounds__(128) void k_kmax(const float* __restrict__ memkv) {
    int row = blockIdx.x;             // b*128 + h*32 + d
    int b = row >> 7;
    int hd = row & 127;
    const float* kp = g_qkv + (size_t)b * QKVROWS * NDIM + (size_t)(HID + hd) * NDIM;
    float m = -INFINITY;
    for (int n = threadIdx.x; n < NDIM; n += 128) m = fmaxf(m, kp[n]);
    __shared__ float red[128];
    red[threadIdx.x] = m;
    __syncthreads();
    for (int s = 64; s > 0; s >>= 1) {
        if (threadIdx.x < s) red[threadIdx.x] = fmaxf(red[threadIdx.x], red[threadIdx.x + s]);
        __syncthreads();
    }
    if (threadIdx.x == 0) {
        float mm = red[0];
        #pragma unroll
        for (int j = 0; j < NMEM; j++) mm = fmaxf(mm, memkv[hd * NMEM + j]);
        g_kmax[row] = mm;
    }
}

// ---------------------------------------------------------------------------
// K3b: per-(b,h): ctx[d,e] = SCALE * (sum_n exp(k[d,n]-max)*v[e,n]) / Z[d]
// incl. memory tokens. One 1024-thread block per (b,h); thread = (e,d).
// ---------------------------------------------------------------------------
__global__ __launch_bounds__(1024) void k_ctx(const float* __restrict__ memkv) {
    __shared__ float ks[32 * 65];
    __shared__ float vs[32 * 65];
    __shared__ float kml[32];
    __shared__ float zrow[32];
    int bh = blockIdx.x;
    int b = bh >> 2, h = bh & 3;
    int tid = threadIdx.x;
    int d = tid & 31, e = tid >> 5;

    const float* base = g_qkv + (size_t)b * QKVROWS * NDIM;
    const float* kp = base + (size_t)(HID + h * ADIM) * NDIM;
    const float* vp = base + (size_t)(2 * HID + h * ADIM) * NDIM;

    if (tid < 32) kml[tid] = g_kmax[b * 128 + h * 32 + tid];
    __syncthreads();

    float km = kml[d];
    float acc = 0.f, zacc = 0.f;
    // memory tokens
    {
        const float* mk = memkv + h * 128 + d * NMEM;
        const float* mv = memkv + 512 + h * 128 + e * NMEM;
        #pragma unroll
        for (int j = 0; j < NMEM; j++) {
            float ek = expf(mk[j] - km);
            acc += ek * mv[j];
            zacc += ek;
        }
    }
    for (int n0 = 0; n0 < NDIM; n0 += 64) {
        __syncthreads();
        #pragma unroll
        for (int idx = tid; idx < 2048; idx += 1024) {
            int r = idx >> 6, c = idx & 63;
            ks[r * 65 + c] = expf(kp[(size_t)r * NDIM + n0 + c] - kml[r]);
            vs[r * 65 + c] = vp[(size_t)r * NDIM + n0 + c];
        }
        __syncthreads();
        const float* kr = ks + d * 65;
        const float* vr = vs + e * 65;
        #pragma unroll 8
        for (int j = 0; j < 64; j++) acc += kr[j] * vr[j];
        if (e == 0) {
            #pragma unroll 8
            for (int j = 0; j < 64; j++) zacc += kr[j];
        }
    }
    if (e == 0) zrow[d] = zacc;
    __syncthreads();
    g_ctx[((size_t)bh * 32 + d) * 32 + e] = acc * SCALE / zrow[d];
}

// ---------------------------------------------------------------------------
// K4: fused: q-softmax(d) -> ctx^T@q -> w_out GEMM + bias -> RMSNorm -> out
// One block per (64-column n tile, batch). 256 threads, ~82KB dyn smem.
// ---------------------------------------------------------------------------
__global__ __launch_bounds__(256) void k_final(const float* __restrict__ w_out,
                                               const float* __restrict__ b_out,
                                               const float* __restrict__ gout,
                                               float* __restrict__ out) {
    extern __shared__ float sm[];
    float* qs = sm;                // [128][64], later reused as ws[16][256]
    float* os = sm + 8192;         // [128][64]
    float* cs = sm + 16384;        // [4][32][32], later reused as red[32][64]
    float* colscale = sm + 20480;  // [64]

    int b = blockIdx.y;
    int n0 = blockIdx.x * 64;
    int tid = threadIdx.x;
    const float* qp = g_qkv + (size_t)b * QKVROWS * NDIM;

    // load q tile (rows 0..127 of qkv) and ctx
    for (int idx = tid; idx < 8192; idx += 256) {
        int r = idx >> 6, c = idx & 63;
        qs[idx] = qp[(size_t)r * NDIM + n0 + c];
    }
    for (int idx = tid; idx < 4096; idx += 256) cs[idx] = g_ctx[b * 4096 + idx];
    __syncthreads();

    // softmax over d per (head, col) — one thread per group
    {
        int h = tid >> 6, c = tid & 63;
        float* col0 = qs + (h * 32) * 64 + c;
        float mx = -INFINITY;
        #pragma unroll
        for (int d = 0; d < 32; d++) mx = fmaxf(mx, col0[d * 64]);
        float s = 0.f;
        #pragma unroll
        for (int d = 0; d < 32; d++) s += expf(col0[d * 64] - mx);
        float inv = 1.f / s;
        #pragma unroll
        for (int d = 0; d < 32; d++) col0[d * 64] = expf(col0[d * 64] - mx) * inv;
    }
    __syncthreads();

    // os[h*32+e][c] = sum_d cs[h][d][e] * qsm[h*32+d][c]
    {
        int h = tid >> 6, c = tid & 63;
        float qreg[32];
        #pragma unroll
        for (int d = 0; d < 32; d++) qreg[d] = qs[(h * 32 + d) * 64 + c];
        const float* ch = cs + h * 1024;
        #pragma unroll
        for (int e = 0; e < 32; e++) {
            float a = 0.f;
            #pragma unroll
            for (int d = 0; d < 32; d++) a += ch[d * 32 + e] * qreg[d];
            os[(h * 32 + e) * 64 + c] = a;
        }
    }
    __syncthreads();   // os ready, qs dead

    // GEMM2: acc[256x64] = w_out(256,128) @ os(128,64)
    float acc[8][8];
    #pragma unroll
    for (int i = 0; i < 8; i++)
        #pragma unroll
        for (int j = 0; j < 8; j++) acc[i][j] = 0.f;
    int tx = tid & 7, ty = tid >> 3;
    float* ws = qs;
    for (int kc = 0; kc < 8; kc++) {
        #pragma unroll
        for (int f = tid; f < 1024; f += 256) {
            int o = f >> 2, c4 = f & 3;
            float4 v = *(const float4*)(w_out + o * HID + kc * 16 + c4 * 4);
            ws[(c4 * 4 + 0) * 256 + o] = v.x;
            ws[(c4 * 4 + 1) * 256 + o] = v.y;
            ws[(c4 * 4 + 2) * 256 + o] = v.z;
            ws[(c4 * 4 + 3) * 256 + o] = v.w;
        }
        __syncthreads();
        #pragma unroll
        for (int kk = 0; kk < 16; kk++) {
            float a[8], bv[8];
            #pragma unroll
            for (int i = 0; i < 8; i++) a[i] = ws[kk * 256 + ty * 8 + i];
            float4 b0 = *(const float4*)&os[(kc * 16 + kk) * 64 + tx * 8];
            float4 b1 = *(const float4*)&os[(kc * 16 + kk) * 64 + tx * 8 + 4];
            bv[0]=b0.x; bv[1]=b0.y; bv[2]=b0.z; bv[3]=b0.w;
            bv[4]=b1.x; bv[5]=b1.y; bv[6]=b1.z; bv[7]=b1.w;
            #pragma unroll
            for (int i = 0; i < 8; i++)
                #pragma unroll
                for (int j = 0; j < 8; j++) acc[i][j] += a[i] * bv[j];
        }
        __syncthreads();
    }

    // bias + per-column sum of squares
    float* red = cs;   // reuse [32][64]
    float bo[8];
    #pragma unroll
    for (int i = 0; i < 8; i++) bo[i] = b_out[ty * 8 + i];
    float part[8];
    #pragma unroll
    for (int j = 0; j < 8; j++) part[j] = 0.f;
    #pragma unroll
    for (int i = 0; i < 8; i++)
        #pragma unroll
        for (int j = 0; j < 8; j++) {
            float v = acc[i][j] + bo[i];
            acc[i][j] = v;
            part[j] += v * v;
        }
    #pragma unroll
    for (int j = 0; j < 8; j++) red[ty * 64 + tx * 8 + j] = part[j];
    __syncthreads();
    if (tid < 64) {
        float s = 0.f;
        #pragma unroll
        for (int t = 0; t < 32; t++) s += red[t * 64 + tid];
        colscale[tid] = 16.0f / fmaxf(sqrtf(s), EPSN);
    }
    __syncthreads();

    float go[8], csj[8];
    #pragma unroll
    for (int i = 0; i < 8; i++) go[i] = gout[ty * 8 + i];
    #pragma unroll
    for (int j = 0; j < 8; j++) csj[j] = colscale[tx * 8 + j];
    float* ob = out + (size_t)b * CDIM * NDIM;
    #pragma unroll
    for (int i = 0; i < 8; i++) {
        int o = ty * 8 + i;
        float gi = go[i];
        float4 v0 = make_float4(acc[i][0]*csj[0]*gi, acc[i][1]*csj[1]*gi,
                                acc[i][2]*csj[2]*gi, acc[i][3]*csj[3]*gi);
        float4 v1 = make_float4(acc[i][4]*csj[4]*gi, acc[i][5]*csj[5]*gi,
                                acc[i][6]*csj[6]*gi, acc[i][7]*csj[7]*gi);
        *(float4*)(ob + (size_t)o * NDIM + n0 + tx * 8)     = v0;
        *(float4*)(ob + (size_t)o * NDIM + n0 + tx * 8 + 4) = v1;
    }
}

// ---------------------------------------------------------------------------
extern "C" void kernel_launch(void* const* d_in, const int* in_sizes, int n_in,
                              void* d_out, int out_size) {
    const float* x      = (const float*)d_in[0];
    const float* norm_g = (const float*)d_in[1];
    const float* w_qkv  = (const float*)d_in[2];
    const float* mem_kv = (const float*)d_in[3];
    const float* w_out  = (const float*)d_in[4];
    const float* b_out  = (const float*)d_in[5];
    const float* out_g  = (const float*)d_in[6];
    float* out = (float*)d_out;

    k_rnorm<<<(BATCH * NDIM) / 256, 256>>>(x);

    dim3 g2(QKVROWS / BM, NDIM / BN, BATCH);
    k_qkv<<<g2, 256>>>(x, w_qkv, norm_g);

    k_kmax<<<BATCH * HEADS * ADIM, 128>>>(mem_kv);
    k_ctx<<<BATCH * HEADS, 1024>>>(mem_kv);

    const int dyn_bytes = (20480 + 64) * (int)sizeof(float);
    cudaFuncSetAttribute(k_final, cudaFuncAttributeMaxDynamicSharedMemorySize, dyn_bytes);
    dim3 g4(NDIM / 64, BATCH);
    k_final<<<g4, 256, dyn_bytes>>>(w_out, b_out, out_g, out);
}

// round 3
// speedup vs baseline: 1.3168x; 1.3168x over previous
#include <cuda_runtime.h>
#include <cuda_bf16.h>
#include <math.h>

// Problem constants
#define BATCH 16
#define CDIM 256
#define NDIM 4096          // 64*64 spatial
#define HEADS 4
#define ADIM 32
#define HID 128            // HEADS*ADIM
#define QKVROWS 384        // 3*HID
#define NMEM 4
#define SCALE 0.17677669529663687f   // 32^-0.5
#define EPSN 1e-12f

// Scratch (device globals: allocation-free per harness rules)
__device__ float g_rnorm[BATCH * NDIM];
__device__ float g_qkv[(size_t)BATCH * QKVROWS * NDIM]; // ~100MB
__device__ float g_kmax[BATCH * HEADS * ADIM];
__device__ float g_ctx[BATCH * HEADS * ADIM * ADIM];    // already * SCALE / Z
__device__ float g_ctx_part[(size_t)32 * 64 * 1024];    // 8MB partials
__device__ float g_z_part[32 * 64 * 32];

// ---------------------------------------------------------------------------
// K1: per-(b,n) inverse channel norm: 16 / max(||x[:,n]||, eps)
// ---------------------------------------------------------------------------
__global__ __launch_bounds__(256) void k_rnorm(const float* __restrict__ x) {
    int idx = blockIdx.x * 256 + threadIdx.x;   // b*NDIM + n
    int b = idx >> 12;
    int n = idx & (NDIM - 1);
    const float* xp = x + (size_t)b * CDIM * NDIM + n;
    float s = 0.f;
    #pragma unroll 8
    for (int c = 0; c < CDIM; c++) {
        float v = xp[(size_t)c * NDIM];
        s += v * v;
    }
    g_rnorm[idx] = 16.0f / fmaxf(sqrtf(s), EPSN);
}

// ---------------------------------------------------------------------------
// K2: qkv[b,o,n] = sum_k (Wqkv[o,k]*g[k]) * x[b,k,n] * rnorm[b,n]
// Classic SGEMM: 128x128 block tile, BK=16, 8x8 per thread.
// ---------------------------------------------------------------------------
#define BM 128
#define BN 128
#define BK 16
__global__ __launch_bounds__(256) void k_qkv(const float* __restrict__ x,
                                             const float* __restrict__ wqkv,
                                             const float* __restrict__ gch) {
    __shared__ float As[BK][BM];
    __shared__ float Bs[BK][BN];
    int b  = blockIdx.z;
    int m0 = blockIdx.x * BM;
    int n0 = blockIdx.y * BN;
    int tid = threadIdx.x;
    int tx = tid & 15, ty = tid >> 4;

    const float* xb = x + (size_t)b * CDIM * NDIM;
    float acc[8][8];
    #pragma unroll
    for (int i = 0; i < 8; i++)
        #pragma unroll
        for (int j = 0; j < 8; j++) acc[i][j] = 0.f;

    for (int k0 = 0; k0 < CDIM; k0 += BK) {
        #pragma unroll
        for (int f = tid; f < 512; f += 256) {
            int row = f >> 2, c4 = f & 3;
            float4 v = *(const float4*)(wqkv + (size_t)(m0 + row) * CDIM + k0 + c4 * 4);
            int kk = c4 * 4;
            As[kk + 0][row] = v.x * gch[k0 + kk + 0];
            As[kk + 1][row] = v.y * gch[k0 + kk + 1];
            As[kk + 2][row] = v.z * gch[k0 + kk + 2];
            As[kk + 3][row] = v.w * gch[k0 + kk + 3];
        }
        #pragma unroll
        for (int f = tid; f < 512; f += 256) {
            int row = f >> 5, c4 = f & 31;
            float4 v = *(const float4*)(xb + (size_t)(k0 + row) * NDIM + n0 + c4 * 4);
            *(float4*)&Bs[row][c4 * 4] = v;
        }
        __syncthreads();
        #pragma unroll
        for (int kk = 0; kk < BK; kk++) {
            float a[8], bb[8];
            float4 a0 = *(const float4*)&As[kk][ty * 8];
            float4 a1 = *(const float4*)&As[kk][ty * 8 + 4];
            a[0]=a0.x; a[1]=a0.y; a[2]=a0.z; a[3]=a0.w;
            a[4]=a1.x; a[5]=a1.y; a[6]=a1.z; a[7]=a1.w;
            float4 b0 = *(const float4*)&Bs[kk][tx * 8];
            float4 b1 = *(const float4*)&Bs[kk][tx * 8 + 4];
            bb[0]=b0.x; bb[1]=b0.y; bb[2]=b0.z; bb[3]=b0.w;
            bb[4]=b1.x; bb[5]=b1.y; bb[6]=b1.z; bb[7]=b1.w;
            #pragma unroll
            for (int i = 0; i < 8; i++)
                #pragma unroll
                for (int j = 0; j < 8; j++) acc[i][j] += a[i] * bb[j];
        }
        __syncthreads();
    }
    float rn[8];
    #pragma unroll
    for (int j = 0; j < 8; j++) rn[j] = g_rnorm[b * NDIM + n0 + tx * 8 + j];
    float* outp = g_qkv + (size_t)b * QKVROWS * NDIM;
    #pragma unroll
    for (int i = 0; i < 8; i++) {
        int o = m0 + ty * 8 + i;
        float4 v0 = make_float4(acc[i][0]*rn[0], acc[i][1]*rn[1], acc[i][2]*rn[2], acc[i][3]*rn[3]);
        float4 v1 = make_float4(acc[i][4]*rn[4], acc[i][5]*rn[5], acc[i][6]*rn[6], acc[i][7]*rn[7]);
        *(float4*)(outp + (size_t)o * NDIM + n0 + tx * 8)     = v0;
        *(float4*)(outp + (size_t)o * NDIM + n0 + tx * 8 + 4) = v1;
    }
}

// ---------------------------------------------------------------------------
// K3a: per-(b,h,d) max over n (including 4 memory tokens)
// ---------------------------------------------------------------------------
__global__ __launch_bounds__(128) void k_kmax(const float* __restrict__ memkv) {
    int row = blockIdx.x;             // b*128 + h*32 + d
    int b = row >> 7;
    int hd = row & 127;
    const float* kp = g_qkv + (size_t)b * QKVROWS * NDIM + (size_t)(HID + hd) * NDIM;
    float m = -INFINITY;
    for (int n = threadIdx.x; n < NDIM; n += 128) m = fmaxf(m, kp[n]);
    __shared__ float red[128];
    red[threadIdx.x] = m;
    __syncthreads();
    for (int s = 64; s > 0; s >>= 1) {
        if (threadIdx.x < s) red[threadIdx.x] = fmaxf(red[threadIdx.x], red[threadIdx.x + s]);
        __syncthreads();
    }
    if (threadIdx.x == 0) {
        float mm = red[0];
        #pragma unroll
        for (int j = 0; j < NMEM; j++) mm = fmaxf(mm, memkv[hd * NMEM + j]);
        g_kmax[row] = mm;
    }
}

// ---------------------------------------------------------------------------
// K3b (stage A): partial ctx over an n-chunk of 512, further split 4-way in j.
// grid = (8 chunks, 64 bh), 256 threads. Thread owns a 4x4 (d,e) register tile
// over a 32-wide j slice. Writes 32 partials per (bh): g_ctx_part[pc][bh][d][e].
// ---------------------------------------------------------------------------
__global__ __launch_bounds__(256) void k_ctx_part() {
    __shared__ float ks[32 * 129];
    __shared__ float vs[32 * 129];
    __shared__ float kml[32];
    int chunk = blockIdx.x;           // 0..7
    int bh = blockIdx.y;              // 0..63
    int b = bh >> 2, h = bh & 3;
    int tid = threadIdx.x;
    int jp = tid >> 6;                // 0..3 j-partition
    int tile = tid & 63;
    int d0 = (tile & 7) * 4;
    int e0 = (tile >> 3) * 4;

    const float* base = g_qkv + (size_t)b * QKVROWS * NDIM;
    const float* kp = base + (size_t)(HID + h * ADIM) * NDIM;
    const float* vp = base + (size_t)(2 * HID + h * ADIM) * NDIM;

    if (tid < 32) kml[tid] = g_kmax[b * 128 + h * 32 + tid];
    __syncthreads();

    float acc[4][4];
    #pragma unroll
    for (int i = 0; i < 4; i++)
        #pragma unroll
        for (int m = 0; m < 4; m++) acc[i][m] = 0.f;
    float zacc[4] = {0.f, 0.f, 0.f, 0.f};

    for (int st = 0; st < 4; st++) {
        int n0 = chunk * 512 + st * 128;
        __syncthreads();
        // load 32 rows x 128 cols of K (exp'd) and V
        #pragma unroll
        for (int f = tid; f < 1024; f += 256) {
            int r = f >> 5, c4 = (f & 31) * 4;
            float km = kml[r];
            float4 kv = *(const float4*)(kp + (size_t)r * NDIM + n0 + c4);
            ks[r * 129 + c4 + 0] = expf(kv.x - km);
            ks[r * 129 + c4 + 1] = expf(kv.y - km);
            ks[r * 129 + c4 + 2] = expf(kv.z - km);
            ks[r * 129 + c4 + 3] = expf(kv.w - km);
            float4 vv = *(const float4*)(vp + (size_t)r * NDIM + n0 + c4);
            vs[r * 129 + c4 + 0] = vv.x;
            vs[r * 129 + c4 + 1] = vv.y;
            vs[r * 129 + c4 + 2] = vv.z;
            vs[r * 129 + c4 + 3] = vv.w;
        }
        __syncthreads();
        #pragma unroll 4
        for (int jj = 0; jj < 32; jj++) {
            int j = jp * 32 + jj;
            float kd[4], vv[4];
            #pragma unroll
            for (int i = 0; i < 4; i++) kd[i] = ks[(d0 + i) * 129 + j];
            #pragma unroll
            for (int m = 0; m < 4; m++) vv[m] = vs[(e0 + m) * 129 + j];
            #pragma unroll
            for (int i = 0; i < 4; i++)
                #pragma unroll
                for (int m = 0; m < 4; m++) acc[i][m] += kd[i] * vv[m];
            if (e0 == 0) {
                #pragma unroll
                for (int i = 0; i < 4; i++) zacc[i] += kd[i];
            }
        }
    }
    int pc = chunk * 4 + jp;          // 0..31
    float* pp = g_ctx_part + ((size_t)pc * 64 + bh) * 1024;
    #pragma unroll
    for (int i = 0; i < 4; i++) {
        float4 v = make_float4(acc[i][0], acc[i][1], acc[i][2], acc[i][3]);
        *(float4*)(pp + (d0 + i) * 32 + e0) = v;
    }
    if (e0 == 0) {
        float* zp = g_z_part + ((size_t)pc * 64 + bh) * 32;
        #pragma unroll
        for (int i = 0; i < 4; i++) zp[d0 + i] = zacc[i];
    }
}

// ---------------------------------------------------------------------------
// K3b (stage B): reduce 32 partials, add memory tokens, fold SCALE / Z.
// grid = 64 (bh), 1024 threads (tid = d*32+e).
// ---------------------------------------------------------------------------
__global__ __launch_bounds__(1024) void k_ctx_reduce(const float* __restrict__ memkv) {
    __shared__ float zs[32];
    int bh = blockIdx.x;
    int b = bh >> 2, h = bh & 3;
    int tid = threadIdx.x;
    int d = tid >> 5, e = tid & 31;

    float acc = 0.f;
    #pragma unroll 8
    for (int c = 0; c < 32; c++)
        acc += g_ctx_part[((size_t)c * 64 + bh) * 1024 + tid];

    float km = g_kmax[b * 128 + h * 32 + d];
    const float* mk = memkv + h * 128 + d * NMEM;
    const float* mv = memkv + 512 + h * 128 + e * NMEM;
    float zmem = 0.f;
    #pragma unroll
    for (int j = 0; j < NMEM; j++) {
        float ek = expf(mk[j] - km);
        acc += ek * mv[j];
        zmem += ek;
    }
    if (e == 0) {
        float z = zmem;
        #pragma unroll 8
        for (int c = 0; c < 32; c++)
            z += g_z_part[((size_t)c * 64 + bh) * 32 + d];
        zs[d] = z;
    }
    __syncthreads();
    g_ctx[(size_t)bh * 1024 + tid] = acc * SCALE / zs[d];
}

// ---------------------------------------------------------------------------
// K4: fused: q-softmax(d) -> ctx^T@q -> w_out GEMM + bias -> RMSNorm -> out
// ---------------------------------------------------------------------------
__global__ __launch_bounds__(256) void k_final(const float* __restrict__ w_out,
                                               const float* __restrict__ b_out,
                                               const float* __restrict__ gout,
                                               float* __restrict__ out) {
    extern __shared__ float sm[];
    float* qs = sm;                // [128][64], later reused as ws[16][256]
    float* os = sm + 8192;         // [128][64]
    float* cs = sm + 16384;        // [4][32][32], later reused as red[32][64]
    float* colscale = sm + 20480;  // [64]

    int b = blockIdx.y;
    int n0 = blockIdx.x * 64;
    int tid = threadIdx.x;
    const float* qp = g_qkv + (size_t)b * QKVROWS * NDIM;

    for (int idx = tid; idx < 8192; idx += 256) {
        int r = idx >> 6, c = idx & 63;
        qs[idx] = qp[(size_t)r * NDIM + n0 + c];
    }
    for (int idx = tid; idx < 4096; idx += 256) cs[idx] = g_ctx[b * 4096 + idx];
    __syncthreads();

    {
        int h = tid >> 6, c = tid & 63;
        float* col0 = qs + (h * 32) * 64 + c;
        float mx = -INFINITY;
        #pragma unroll
        for (int d = 0; d < 32; d++) mx = fmaxf(mx, col0[d * 64]);
        float s = 0.f;
        #pragma unroll
        for (int d = 0; d < 32; d++) s += expf(col0[d * 64] - mx);
        float inv = 1.f / s;
        #pragma unroll
        for (int d = 0; d < 32; d++) col0[d * 64] = expf(col0[d * 64] - mx) * inv;
    }
    __syncthreads();

    {
        int h = tid >> 6, c = tid & 63;
        float qreg[32];
        #pragma unroll
        for (int d = 0; d < 32; d++) qreg[d] = qs[(h * 32 + d) * 64 + c];
        const float* ch = cs + h * 1024;
        #pragma unroll
        for (int e = 0; e < 32; e++) {
            float a = 0.f;
            #pragma unroll
            for (int d = 0; d < 32; d++) a += ch[d * 32 + e] * qreg[d];
            os[(h * 32 + e) * 64 + c] = a;
        }
    }
    __syncthreads();

    float acc[8][8];
    #pragma unroll
    for (int i = 0; i < 8; i++)
        #pragma unroll
        for (int j = 0; j < 8; j++) acc[i][j] = 0.f;
    int tx = tid & 7, ty = tid >> 3;
    float* ws = qs;
    for (int kc = 0; kc < 8; kc++) {
        #pragma unroll
        for (int f = tid; f < 1024; f += 256) {
            int o = f >> 2, c4 = f & 3;
            float4 v = *(const float4*)(w_out + o * HID + kc * 16 + c4 * 4);
            ws[(c4 * 4 + 0) * 256 + o] = v.x;
            ws[(c4 * 4 + 1) * 256 + o] = v.y;
            ws[(c4 * 4 + 2) * 256 + o] = v.z;
            ws[(c4 * 4 + 3) * 256 + o] = v.w;
        }
        __syncthreads();
        #pragma unroll
        for (int kk = 0; kk < 16; kk++) {
            float a[8], bv[8];
            #pragma unroll
            for (int i = 0; i < 8; i++) a[i] = ws[kk * 256 + ty * 8 + i];
            float4 b0 = *(const float4*)&os[(kc * 16 + kk) * 64 + tx * 8];
            float4 b1 = *(const float4*)&os[(kc * 16 + kk) * 64 + tx * 8 + 4];
            bv[0]=b0.x; bv[1]=b0.y; bv[2]=b0.z; bv[3]=b0.w;
            bv[4]=b1.x; bv[5]=b1.y; bv[6]=b1.z; bv[7]=b1.w;
            #pragma unroll
            for (int i = 0; i < 8; i++)
                #pragma unroll
                for (int j = 0; j < 8; j++) acc[i][j] += a[i] * bv[j];
        }
        __syncthreads();
    }

    float* red = cs;
    float bo[8];
    #pragma unroll
    for (int i = 0; i < 8; i++) bo[i] = b_out[ty * 8 + i];
    float part[8];
    #pragma unroll
    for (int j = 0; j < 8; j++) part[j] = 0.f;
    #pragma unroll
    for (int i = 0; i < 8; i++)
        #pragma unroll
        for (int j = 0; j < 8; j++) {
            float v = acc[i][j] + bo[i];
            acc[i][j] = v;
            part[j] += v * v;
        }
    #pragma unroll
    for (int j = 0; j < 8; j++) red[ty * 64 + tx * 8 + j] = part[j];
    __syncthreads();
    if (tid < 64) {
        float s = 0.f;
        #pragma unroll
        for (int t = 0; t < 32; t++) s += red[t * 64 + tid];
        colscale[tid] = 16.0f / fmaxf(sqrtf(s), EPSN);
    }
    __syncthreads();

    float go[8], csj[8];
    #pragma unroll
    for (int i = 0; i < 8; i++) go[i] = gout[ty * 8 + i];
    #pragma unroll
    for (int j = 0; j < 8; j++) csj[j] = colscale[tx * 8 + j];
    float* ob = out + (size_t)b * CDIM * NDIM;
    #pragma unroll
    for (int i = 0; i < 8; i++) {
        int o = ty * 8 + i;
        float gi = go[i];
        float4 v0 = make_float4(acc[i][0]*csj[0]*gi, acc[i][1]*csj[1]*gi,
                                acc[i][2]*csj[2]*gi, acc[i][3]*csj[3]*gi);
        float4 v1 = make_float4(acc[i][4]*csj[4]*gi, acc[i][5]*csj[5]*gi,
                                acc[i][6]*csj[6]*gi, acc[i][7]*csj[7]*gi);
        *(float4*)(ob + (size_t)o * NDIM + n0 + tx * 8)     = v0;
        *(float4*)(ob + (size_t)o * NDIM + n0 + tx * 8 + 4) = v1;
    }
}

// ---------------------------------------------------------------------------
extern "C" void kernel_launch(void* const* d_in, const int* in_sizes, int n_in,
                              void* d_out, int out_size) {
    const float* x      = (const float*)d_in[0];
    const float* norm_g = (const float*)d_in[1];
    const float* w_qkv  = (const float*)d_in[2];
    const float* mem_kv = (const float*)d_in[3];
    const float* w_out  = (const float*)d_in[4];
    const float* b_out  = (const float*)d_in[5];
    const float* out_g  = (const float*)d_in[6];
    float* out = (float*)d_out;

    k_rnorm<<<(BATCH * NDIM) / 256, 256>>>(x);

    dim3 g2(QKVROWS / BM, NDIM / BN, BATCH);
    k_qkv<<<g2, 256>>>(x, w_qkv, norm_g);

    k_kmax<<<BATCH * HEADS * ADIM, 128>>>(mem_kv);

    dim3 g3(8, 64);
    k_ctx_part<<<g3, 256>>>();
    k_ctx_reduce<<<BATCH * HEADS, 1024>>>(mem_kv);

    const int dyn_bytes = (20480 + 64) * (int)sizeof(float);
    cudaFuncSetAttribute(k_final, cudaFuncAttributeMaxDynamicSharedMemorySize, dyn_bytes);
    dim3 g4(NDIM / 64, BATCH);
    k_final<<<g4, 256, dyn_bytes>>>(w_out, b_out, out_g, out);
}

// round 5
// speedup vs baseline: 1.8905x; 1.4357x over previous
#include <cuda_runtime.h>
#include <cuda_bf16.h>
#include <math.h>
#include <stdint.h>

// Problem constants
#define BATCH 16
#define CDIM 256
#define NDIM 4096          // 64*64 spatial
#define HEADS 4
#define ADIM 32
#define HID 128
#define QKVROWS 384        // 3*HID
#define NMEM 4
#define SCALE 0.17677669529663687f   // 32^-0.5
#define EPSN 1e-12f

// Scratch (device globals: allocation-free per harness rules)
__device__ float g_rnorm[BATCH * NDIM];
__device__ float g_qkv[(size_t)BATCH * QKVROWS * NDIM]; // ~100MB
__device__ float g_kmax[BATCH * HEADS * ADIM];
__device__ float g_ctx[BATCH * HEADS * ADIM * ADIM];    // already * SCALE / Z
__device__ float g_ctx_part[(size_t)32 * 64 * 1024];    // 8MB partials
__device__ float g_z_part[32 * 64 * 32];
// Pre-split bf16 operands (k-contiguous rows)
__device__ __nv_bfloat16 g_wh[QKVROWS * CDIM];
__device__ __nv_bfloat16 g_wl[QKVROWS * CDIM];
__device__ __nv_bfloat16 g_xh[(size_t)BATCH * NDIM * CDIM];  // [b][n][c]
__device__ __nv_bfloat16 g_xl[(size_t)BATCH * NDIM * CDIM];

// ---------------------------------------------------------------------------
__device__ __forceinline__ uint32_t smem_u32(const void* p) {
    uint32_t a;
    asm("{ .reg .u64 t; cvta.to.shared.u64 t, %1; cvt.u32.u64 %0, t; }" : "=r"(a) : "l"(p));
    return a;
}
#define CP_ASYNC16(saddr, gaddr) \
    asm volatile("cp.async.cg.shared.global [%0], [%1], 16;" :: "r"(saddr), "l"(gaddr) : "memory")
#define CP_COMMIT() asm volatile("cp.async.commit_group;" ::: "memory")
#define CP_WAIT(n)  asm volatile("cp.async.wait_group %0;" :: "n"(n) : "memory")

#define LDMATRIX_X4(r0, r1, r2, r3, addr) \
    asm volatile("ldmatrix.sync.aligned.m8n8.x4.shared.b16 {%0,%1,%2,%3}, [%4];" \
                 : "=r"(r0), "=r"(r1), "=r"(r2), "=r"(r3) : "r"(addr))
#define LDMATRIX_X2(r0, r1, addr) \
    asm volatile("ldmatrix.sync.aligned.m8n8.x2.shared.b16 {%0,%1}, [%2];" \
                 : "=r"(r0), "=r"(r1) : "r"(addr))
#define MMA_BF16(d0, d1, d2, d3, a0, a1, a2, a3, b0, b1) \
    asm volatile("mma.sync.aligned.m16n8k16.row.col.f32.bf16.bf16.f32 " \
                 "{%0,%1,%2,%3}, {%4,%5,%6,%7}, {%8,%9}, {%0,%1,%2,%3};" \
                 : "+f"(d0), "+f"(d1), "+f"(d2), "+f"(d3) \
                 : "r"(a0), "r"(a1), "r"(a2), "r"(a3), "r"(b0), "r"(b1))

// ---------------------------------------------------------------------------
// K1: per-(b,n) inverse channel norm: 16 / max(||x[:,n]||, eps)
// ---------------------------------------------------------------------------
__global__ __launch_bounds__(256) void k_rnorm(const float* __restrict__ x) {
    int idx = blockIdx.x * 256 + threadIdx.x;   // b*NDIM + n
    int b = idx >> 12;
    int n = idx & (NDIM - 1);
    const float* xp = x + (size_t)b * CDIM * NDIM + n;
    float s = 0.f;
    #pragma unroll 8
    for (int c = 0; c < CDIM; c++) {
        float v = xp[(size_t)c * NDIM];
        s += v * v;
    }
    g_rnorm[idx] = 16.0f / fmaxf(sqrtf(s), EPSN);
}

// ---------------------------------------------------------------------------
// K1b: W*g -> bf16 hi/lo, [o][k] row-major
// ---------------------------------------------------------------------------
__global__ __launch_bounds__(256) void k_wsplit(const float* __restrict__ wqkv,
                                                const float* __restrict__ gch) {
    int e = blockIdx.x * 256 + threadIdx.x;     // 0 .. 384*256-1
    int r = e >> 8, k = e & 255;
    float w = wqkv[r * CDIM + k] * gch[k];
    __nv_bfloat16 hi = __float2bfloat16(w);
    __nv_bfloat16 lo = __float2bfloat16(w - __bfloat162float(hi));
    g_wh[e] = hi;
    g_wl[e] = lo;
    (void)r;
}

// ---------------------------------------------------------------------------
// K1c: x*rnorm -> transposed bf16 hi/lo [b][n][c] (k-contiguous)
// 64x64 tile per block, 256 threads.
// ---------------------------------------------------------------------------
__global__ __launch_bounds__(256) void k_xsplit(const float* __restrict__ x) {
    __shared__ float s[64][65];
    int n0 = blockIdx.x * 64;
    int c0 = blockIdx.y * 64;
    int b  = blockIdx.z;
    int tid = threadIdx.x;
    const float* xb = x + (size_t)b * CDIM * NDIM;

    #pragma unroll
    for (int idx = tid; idx < 1024; idx += 256) {
        int row = idx >> 4, ch = idx & 15;      // c-row, n-chunk
        float4 v = *(const float4*)(xb + (size_t)(c0 + row) * NDIM + n0 + ch * 4);
        s[row][ch * 4 + 0] = v.x;
        s[row][ch * 4 + 1] = v.y;
        s[row][ch * 4 + 2] = v.z;
        s[row][ch * 4 + 3] = v.w;
    }
    __syncthreads();

    #pragma unroll
    for (int idx = tid; idx < 2048; idx += 256) {
        int nr = idx >> 5, cp = idx & 31;       // out n-row, c-pair
        float rn = g_rnorm[b * NDIM + n0 + nr];
        float v0 = s[cp * 2 + 0][nr] * rn;
        float v1 = s[cp * 2 + 1][nr] * rn;
        __nv_bfloat16 h0 = __float2bfloat16(v0);
        __nv_bfloat16 h1 = __float2bfloat16(v1);
        __nv_bfloat16 l0 = __float2bfloat16(v0 - __bfloat162float(h0));
        __nv_bfloat16 l1 = __float2bfloat16(v1 - __bfloat162float(h1));
        uint32_t hp = (uint32_t)*(uint16_t*)&h0 | ((uint32_t)*(uint16_t*)&h1 << 16);
        uint32_t lp = (uint32_t)*(uint16_t*)&l0 | ((uint32_t)*(uint16_t*)&l1 << 16);
        size_t o = ((size_t)b * NDIM + n0 + nr) * CDIM + c0 + cp * 2;
        *(uint32_t*)&g_xh[o] = hp;
        *(uint32_t*)&g_xl[o] = lp;
    }
}

// ---------------------------------------------------------------------------
// K2: QKV GEMM via mma.sync bf16 (split-bf16, 3 terms).
// Block tile 128x128, BK=32, double-buffered cp.async.
// Warp grid 2(m) x 4(n): each warp 64x32.
// smem row = 32 bf16 + 8 pad = 80B (ldmatrix conflict-free).
// ---------------------------------------------------------------------------
#define RS 80
#define T_AH 0
#define T_AL 10240
#define T_BH 20480
#define T_BL 30720
#define STG  40960

__global__ __launch_bounds__(256) void k_qkv_mma() {
    extern __shared__ char smem[];
    uint32_t sb = smem_u32(smem);
    int tid = threadIdx.x;
    int lane = tid & 31, wid = tid >> 5;
    int wm = wid & 1, wn = wid >> 1;
    int m0 = blockIdx.x * 128;
    int n0 = blockIdx.y * 128;
    int b  = blockIdx.z;

    const __nv_bfloat16* xhb = g_xh + (size_t)b * NDIM * CDIM;
    const __nv_bfloat16* xlb = g_xl + (size_t)b * NDIM * CDIM;

    float acc[4][4][4];
    #pragma unroll
    for (int i = 0; i < 4; i++)
        #pragma unroll
        for (int j = 0; j < 4; j++)
            #pragma unroll
            for (int r = 0; r < 4; r++) acc[i][j][r] = 0.f;

    // stage copy lambda-ish macro: 2048 16B chunks
    auto issue_stage = [&](int s) {
        int k0 = s * 32;
        uint32_t dst_base = sb + (s & 1) * STG;
        #pragma unroll
        for (int t = 0; t < 8; t++) {
            int idx = tid + t * 256;
            int tile = idx >> 9;
            int i = idx & 511;
            int row = i >> 2, pos = i & 3;
            uint32_t daddr = dst_base + tile * 10240 + row * RS + pos * 16;
            const __nv_bfloat16* src;
            if (tile == 0)      src = g_wh + (size_t)(m0 + row) * CDIM + k0 + pos * 8;
            else if (tile == 1) src = g_wl + (size_t)(m0 + row) * CDIM + k0 + pos * 8;
            else if (tile == 2) src = xhb + (size_t)(n0 + row) * CDIM + k0 + pos * 8;
            else                src = xlb + (size_t)(n0 + row) * CDIM + k0 + pos * 8;
            CP_ASYNC16(daddr, src);
        }
        CP_COMMIT();
    };

    issue_stage(0);
    for (int s = 0; s < 8; s++) {
        if (s + 1 < 8) {
            issue_stage(s + 1);
            CP_WAIT(1);
        } else {
            CP_WAIT(0);
        }
        __syncthreads();
        uint32_t buf = sb + (s & 1) * STG;

        #pragma unroll
        for (int ks = 0; ks < 2; ks++) {
            uint32_t ah[4][4], al[4][4], bh[4][2], bl[4][2];
            int akoff = (ks * 16 + (lane >> 4) * 8) * 2;
            int arow = (lane & 15);
            #pragma unroll
            for (int mi = 0; mi < 4; mi++) {
                int rb = wm * 64 + mi * 16 + arow;
                uint32_t ad = buf + T_AH + rb * RS + akoff;
                LDMATRIX_X4(ah[mi][0], ah[mi][1], ah[mi][2], ah[mi][3], ad);
                uint32_t ad2 = buf + T_AL + rb * RS + akoff;
                LDMATRIX_X4(al[mi][0], al[mi][1], al[mi][2], al[mi][3], ad2);
            }
            int l = lane & 15;
            int bkoff = (ks * 16 + (l >> 3) * 8) * 2;
            int brow = l & 7;
            #pragma unroll
            for (int ni = 0; ni < 4; ni++) {
                int rb = wn * 32 + ni * 8 + brow;
                uint32_t bd = buf + T_BH + rb * RS + bkoff;
                LDMATRIX_X2(bh[ni][0], bh[ni][1], bd);
                uint32_t bd2 = buf + T_BL + rb * RS + bkoff;
                LDMATRIX_X2(bl[ni][0], bl[ni][1], bd2);
            }
            // term 1: Ah*Bh
            #pragma unroll
            for (int mi = 0; mi < 4; mi++)
                #pragma unroll
                for (int ni = 0; ni < 4; ni++)
                    MMA_BF16(acc[mi][ni][0], acc[mi][ni][1], acc[mi][ni][2], acc[mi][ni][3],
                             ah[mi][0], ah[mi][1], ah[mi][2], ah[mi][3], bh[ni][0], bh[ni][1]);
            // term 2: Ah*Bl
            #pragma unroll
            for (int mi = 0; mi < 4; mi++)
                #pragma unroll
                for (int ni = 0; ni < 4; ni++)
                    MMA_BF16(acc[mi][ni][0], acc[mi][ni][1], acc[mi][ni][2], acc[mi][ni][3],
                             ah[mi][0], ah[mi][1], ah[mi][2], ah[mi][3], bl[ni][0], bl[ni][1]);
            // term 3: Al*Bh
            #pragma unroll
            for (int mi = 0; mi < 4; mi++)
                #pragma unroll
                for (int ni = 0; ni < 4; ni++)
                    MMA_BF16(acc[mi][ni][0], acc[mi][ni][1], acc[mi][ni][2], acc[mi][ni][3],
                             al[mi][0], al[mi][1], al[mi][2], al[mi][3], bh[ni][0], bh[ni][1]);
        }
        __syncthreads();
    }

    // epilogue: d-frag mapping -> g_qkv fp32
    float* outp = g_qkv + (size_t)b * QKVROWS * NDIM;
    int tr = lane >> 2, tc = (lane & 3) * 2;
    #pragma unroll
    for (int mi = 0; mi < 4; mi++) {
        #pragma unroll
        for (int ni = 0; ni < 4; ni++) {
            int o0 = m0 + wm * 64 + mi * 16 + tr;
            int nn = n0 + wn * 32 + ni * 8 + tc;
            float2 v0 = make_float2(acc[mi][ni][0], acc[mi][ni][1]);
            float2 v1 = make_float2(acc[mi][ni][2], acc[mi][ni][3]);
            *(float2*)(outp + (size_t)o0 * NDIM + nn)       = v0;
            *(float2*)(outp + (size_t)(o0 + 8) * NDIM + nn) = v1;
        }
    }
}

// ---------------------------------------------------------------------------
// K3a: per-(b,h,d) max over n (including 4 memory tokens)
// ---------------------------------------------------------------------------
__global__ __launch_bounds__(128) void k_kmax(const float* __restrict__ memkv) {
    int row = blockIdx.x;             // b*128 + h*32 + d
    int b = row >> 7;
    int hd = row & 127;
    const float* kp = g_qkv + (size_t)b * QKVROWS * NDIM + (size_t)(HID + hd) * NDIM;
    float m = -INFINITY;
    for (int n = threadIdx.x; n < NDIM; n += 128) m = fmaxf(m, kp[n]);
    __shared__ float red[128];
    red[threadIdx.x] = m;
    __syncthreads();
    for (int s = 64; s > 0; s >>= 1) {
        if (threadIdx.x < s) red[threadIdx.x] = fmaxf(red[threadIdx.x], red[threadIdx.x + s]);
        __syncthreads();
    }
    if (threadIdx.x == 0) {
        float mm = red[0];
        #pragma unroll
        for (int j = 0; j < NMEM; j++) mm = fmaxf(mm, memkv[hd * NMEM + j]);
        g_kmax[row] = mm;
    }
}

// ---------------------------------------------------------------------------
// K3b (stage A): partial ctx over an n-chunk of 512, split 4-way in j.
// ---------------------------------------------------------------------------
__global__ __launch_bounds__(256) void k_ctx_part() {
    __shared__ float ks[32 * 129];
    __shared__ float vs[32 * 129];
    __shared__ float kml[32];
    int chunk = blockIdx.x;           // 0..7
    int bh = blockIdx.y;              // 0..63
    int b = bh >> 2, h = bh & 3;
    int tid = threadIdx.x;
    int jp = tid >> 6;                // 0..3 j-partition
    int tile = tid & 63;
    int d0 = (tile & 7) * 4;
    int e0 = (tile >> 3) * 4;

    const float* base = g_qkv + (size_t)b * QKVROWS * NDIM;
    const float* kp = base + (size_t)(HID + h * ADIM) * NDIM;
    const float* vp = base + (size_t)(2 * HID + h * ADIM) * NDIM;

    if (tid < 32) kml[tid] = g_kmax[b * 128 + h * 32 + tid];
    __syncthreads();

    float acc[4][4];
    #pragma unroll
    for (int i = 0; i < 4; i++)
        #pragma unroll
        for (int m = 0; m < 4; m++) acc[i][m] = 0.f;
    float zacc[4] = {0.f, 0.f, 0.f, 0.f};

    for (int st = 0; st < 4; st++) {
        int n0 = chunk * 512 + st * 128;
        __syncthreads();
        #pragma unroll
        for (int f = tid; f < 1024; f += 256) {
            int r = f >> 5, c4 = (f & 31) * 4;
            float km = kml[r];
            float4 kv = *(const float4*)(kp + (size_t)r * NDIM + n0 + c4);
            ks[r * 129 + c4 + 0] = expf(kv.x - km);
            ks[r * 129 + c4 + 1] = expf(kv.y - km);
            ks[r * 129 + c4 + 2] = expf(kv.z - km);
            ks[r * 129 + c4 + 3] = expf(kv.w - km);
            float4 vv = *(const float4*)(vp + (size_t)r * NDIM + n0 + c4);
            vs[r * 129 + c4 + 0] = vv.x;
            vs[r * 129 + c4 + 1] = vv.y;
            vs[r * 129 + c4 + 2] = vv.z;
            vs[r * 129 + c4 + 3] = vv.w;
        }
        __syncthreads();
        #pragma unroll 4
        for (int jj = 0; jj < 32; jj++) {
            int j = jp * 32 + jj;
            float kd[4], vv[4];
            #pragma unroll
            for (int i = 0; i < 4; i++) kd[i] = ks[(d0 + i) * 129 + j];
            #pragma unroll
            for (int m = 0; m < 4; m++) vv[m] = vs[(e0 + m) * 129 + j];
            #pragma unroll
            for (int i = 0; i < 4; i++)
                #pragma unroll
                for (int m = 0; m < 4; m++) acc[i][m] += kd[i] * vv[m];
            if (e0 == 0) {
                #pragma unroll
                for (int i = 0; i < 4; i++) zacc[i] += kd[i];
            }
        }
    }
    int pc = chunk * 4 + jp;
    float* pp = g_ctx_part + ((size_t)pc * 64 + bh) * 1024;
    #pragma unroll
    for (int i = 0; i < 4; i++) {
        float4 v = make_float4(acc[i][0], acc[i][1], acc[i][2], acc[i][3]);
        *(float4*)(pp + (d0 + i) * 32 + e0) = v;
    }
    if (e0 == 0) {
        float* zp = g_z_part + ((size_t)pc * 64 + bh) * 32;
        #pragma unroll
        for (int i = 0; i < 4; i++) zp[d0 + i] = zacc[i];
    }
}

// ---------------------------------------------------------------------------
// K3b (stage B): reduce 32 partials, add memory tokens, fold SCALE / Z.
// ---------------------------------------------------------------------------
__global__ __launch_bounds__(1024) void k_ctx_reduce(const float* __restrict__ memkv) {
    __shared__ float zs[32];
    int bh = blockIdx.x;
    int b = bh >> 2, h = bh & 3;
    int tid = threadIdx.x;
    int d = tid >> 5, e = tid & 31;

    float acc = 0.f;
    #pragma unroll 8
    for (int c = 0; c < 32; c++)
        acc += g_ctx_part[((size_t)c * 64 + bh) * 1024 + tid];

    float km = g_kmax[b * 128 + h * 32 + d];
    const float* mk = memkv + h * 128 + d * NMEM;
    const float* mv = memkv + 512 + h * 128 + e * NMEM;
    float zmem = 0.f;
    #pragma unroll
    for (int j = 0; j < NMEM; j++) {
        float ek = expf(mk[j] - km);
        acc += ek * mv[j];
        zmem += ek;
    }
    if (e == 0) {
        float z = zmem;
        #pragma unroll 8
        for (int c = 0; c < 32; c++)
            z += g_z_part[((size_t)c * 64 + bh) * 32 + d];
        zs[d] = z;
    }
    __syncthreads();
    g_ctx[(size_t)bh * 1024 + tid] = acc * SCALE / zs[d];
}

// ---------------------------------------------------------------------------
// K4: fused: q-softmax(d) -> ctx^T@q -> w_out GEMM + bias -> RMSNorm -> out
// ---------------------------------------------------------------------------
__global__ __launch_bounds__(256) void k_final(const float* __restrict__ w_out,
                                               const float* __restrict__ b_out,
                                               const float* __restrict__ gout,
                                               float* __restrict__ out) {
    extern __shared__ float sm[];
    float* qs = sm;                // [128][64], later reused as ws[16][256]
    float* os = sm + 8192;         // [128][64]
    float* cs = sm + 16384;        // [4][32][32], later reused as red[32][64]
    float* colscale = sm + 20480;  // [64]

    int b = blockIdx.y;
    int n0 = blockIdx.x * 64;
    int tid = threadIdx.x;
    const float* qp = g_qkv + (size_t)b * QKVROWS * NDIM;

    for (int idx = tid; idx < 8192; idx += 256) {
        int r = idx >> 6, c = idx & 63;
        qs[idx] = qp[(size_t)r * NDIM + n0 + c];
    }
    for (int idx = tid; idx < 4096; idx += 256) cs[idx] = g_ctx[b * 4096 + idx];
    __syncthreads();

    {
        int h = tid >> 6, c = tid & 63;
        float* col0 = qs + (h * 32) * 64 + c;
        float mx = -INFINITY;
        #pragma unroll
        for (int d = 0; d < 32; d++) mx = fmaxf(mx, col0[d * 64]);
        float s = 0.f;
        #pragma unroll
        for (int d = 0; d < 32; d++) s += expf(col0[d * 64] - mx);
        float inv = 1.f / s;
        #pragma unroll
        for (int d = 0; d < 32; d++) col0[d * 64] = expf(col0[d * 64] - mx) * inv;
    }
    __syncthreads();

    {
        int h = tid >> 6, c = tid & 63;
        float qreg[32];
        #pragma unroll
        for (int d = 0; d < 32; d++) qreg[d] = qs[(h * 32 + d) * 64 + c];
        const float* ch = cs + h * 1024;
        #pragma unroll
        for (int e = 0; e < 32; e++) {
            float a = 0.f;
            #pragma unroll
            for (int d = 0; d < 32; d++) a += ch[d * 32 + e] * qreg[d];
            os[(h * 32 + e) * 64 + c] = a;
        }
    }
    __syncthreads();

    float acc[8][8];
    #pragma unroll
    for (int i = 0; i < 8; i++)
        #pragma unroll
        for (int j = 0; j < 8; j++) acc[i][j] = 0.f;
    int tx = tid & 7, ty = tid >> 3;
    float* ws = qs;
    for (int kc = 0; kc < 8; kc++) {
        #pragma unroll
        for (int f = tid; f < 1024; f += 256) {
            int o = f >> 2, c4 = f & 3;
            float4 v = *(const float4*)(w_out + o * HID + kc * 16 + c4 * 4);
            ws[(c4 * 4 + 0) * 256 + o] = v.x;
            ws[(c4 * 4 + 1) * 256 + o] = v.y;
            ws[(c4 * 4 + 2) * 256 + o] = v.z;
            ws[(c4 * 4 + 3) * 256 + o] = v.w;
        }
        __syncthreads();
        #pragma unroll
        for (int kk = 0; kk < 16; kk++) {
            float a[8], bv[8];
            #pragma unroll
            for (int i = 0; i < 8; i++) a[i] = ws[kk * 256 + ty * 8 + i];
            float4 b0 = *(const float4*)&os[(kc * 16 + kk) * 64 + tx * 8];
            float4 b1 = *(const float4*)&os[(kc * 16 + kk) * 64 + tx * 8 + 4];
            bv[0]=b0.x; bv[1]=b0.y; bv[2]=b0.z; bv[3]=b0.w;
            bv[4]=b1.x; bv[5]=b1.y; bv[6]=b1.z; bv[7]=b1.w;
            #pragma unroll
            for (int i = 0; i < 8; i++)
                #pragma unroll
                for (int j = 0; j < 8; j++) acc[i][j] += a[i] * bv[j];
        }
        __syncthreads();
    }

    float* red = cs;
    float bo[8];
    #pragma unroll
    for (int i = 0; i < 8; i++) bo[i] = b_out[ty * 8 + i];
    float part[8];
    #pragma unroll
    for (int j = 0; j < 8; j++) part[j] = 0.f;
    #pragma unroll
    for (int i = 0; i < 8; i++)
        #pragma unroll
        for (int j = 0; j < 8; j++) {
            float v = acc[i][j] + bo[i];
            acc[i][j] = v;
            part[j] += v * v;
        }
    #pragma unroll
    for (int j = 0; j < 8; j++) red[ty * 64 + tx * 8 + j] = part[j];
    __syncthreads();
    if (tid < 64) {
        float s = 0.f;
        #pragma unroll
        for (int t = 0; t < 32; t++) s += red[t * 64 + tid];
        colscale[tid] = 16.0f / fmaxf(sqrtf(s), EPSN);
    }
    __syncthreads();

    float go[8], csj[8];
    #pragma unroll
    for (int i = 0; i < 8; i++) go[i] = gout[ty * 8 + i];
    #pragma unroll
    for (int j = 0; j < 8; j++) csj[j] = colscale[tx * 8 + j];
    float* ob = out + (size_t)b * CDIM * NDIM;
    #pragma unroll
    for (int i = 0; i < 8; i++) {
        int o = ty * 8 + i;
        float gi = go[i];
        float4 v0 = make_float4(acc[i][0]*csj[0]*gi, acc[i][1]*csj[1]*gi,
                                acc[i][2]*csj[2]*gi, acc[i][3]*csj[3]*gi);
        float4 v1 = make_float4(acc[i][4]*csj[4]*gi, acc[i][5]*csj[5]*gi,
                                acc[i][6]*csj[6]*gi, acc[i][7]*csj[7]*gi);
        *(float4*)(ob + (size_t)o * NDIM + n0 + tx * 8)     = v0;
        *(float4*)(ob + (size_t)o * NDIM + n0 + tx * 8 + 4) = v1;
    }
}

// ---------------------------------------------------------------------------
extern "C" void kernel_launch(void* const* d_in, const int* in_sizes, int n_in,
                              void* d_out, int out_size) {
    const float* x      = (const float*)d_in[0];
    const float* norm_g = (const float*)d_in[1];
    const float* w_qkv  = (const float*)d_in[2];
    const float* mem_kv = (const float*)d_in[3];
    const float* w_out  = (const float*)d_in[4];
    const float* b_out  = (const float*)d_in[5];
    const float* out_g  = (const float*)d_in[6];
    float* out = (float*)d_out;

    k_rnorm<<<(BATCH * NDIM) / 256, 256>>>(x);
    k_wsplit<<<(QKVROWS * CDIM) / 256, 256>>>(w_qkv, norm_g);

    dim3 gx(NDIM / 64, CDIM / 64, BATCH);
    k_xsplit<<<gx, 256>>>(x);

    cudaFuncSetAttribute(k_qkv_mma, cudaFuncAttributeMaxDynamicSharedMemorySize, 2 * STG);
    dim3 g2(QKVROWS / 128, NDIM / 128, BATCH);
    k_qkv_mma<<<g2, 256, 2 * STG>>>();

    k_kmax<<<BATCH * HEADS * ADIM, 128>>>(mem_kv);

    dim3 g3(8, 64);
    k_ctx_part<<<g3, 256>>>();
    k_ctx_reduce<<<BATCH * HEADS, 1024>>>(mem_kv);

    const int dyn_bytes = (20480 + 64) * (int)sizeof(float);
    cudaFuncSetAttribute(k_final, cudaFuncAttributeMaxDynamicSharedMemorySize, dyn_bytes);
    dim3 g4(NDIM / 64, BATCH);
    k_final<<<g4, 256, dyn_bytes>>>(w_out, b_out, out_g, out);
}

// round 6
// speedup vs baseline: 2.2232x; 1.1759x over previous
#include <cuda_runtime.h>
#include <cuda_bf16.h>
#include <math.h>
#include <stdint.h>

// Problem constants
#define BATCH 16
#define CDIM 256
#define NDIM 4096          // 64*64 spatial
#define HEADS 4
#define ADIM 32
#define HID 128
#define QKVROWS 384        // 3*HID
#define NMEM 4
#define SCALE 0.17677669529663687f   // 32^-0.5
#define EPSN 1e-12f

// Scratch (device globals: allocation-free per harness rules)
__device__ float g_rnorm[BATCH * NDIM];
__device__ float g_qkv[(size_t)BATCH * QKVROWS * NDIM]; // ~100MB
__device__ float g_kmax[BATCH * HEADS * ADIM];
__device__ float g_ctx[BATCH * HEADS * ADIM * ADIM];    // already * SCALE / Z
__device__ float g_ctx_part[(size_t)32 * 64 * 1024];    // 8MB partials
__device__ float g_z_part[32 * 64 * 32];
// Pre-split bf16 operands (k-contiguous rows)
__device__ __nv_bfloat16 g_wh[QKVROWS * CDIM];
__device__ __nv_bfloat16 g_wl[QKVROWS * CDIM];
__device__ __nv_bfloat16 g_xh[(size_t)BATCH * NDIM * CDIM];  // [b][n][c]
__device__ __nv_bfloat16 g_xl[(size_t)BATCH * NDIM * CDIM];
// Pre-split w_out (256 x 128)
__device__ __nv_bfloat16 g_woh[CDIM * HID];
__device__ __nv_bfloat16 g_wol[CDIM * HID];

// ---------------------------------------------------------------------------
__device__ __forceinline__ uint32_t smem_u32(const void* p) {
    uint32_t a;
    asm("{ .reg .u64 t; cvta.to.shared.u64 t, %1; cvt.u32.u64 %0, t; }" : "=r"(a) : "l"(p));
    return a;
}
#define CP_ASYNC16(saddr, gaddr) \
    asm volatile("cp.async.cg.shared.global [%0], [%1], 16;" :: "r"(saddr), "l"(gaddr) : "memory")
#define CP_COMMIT() asm volatile("cp.async.commit_group;" ::: "memory")
#define CP_WAIT(n)  asm volatile("cp.async.wait_group %0;" :: "n"(n) : "memory")

#define LDMATRIX_X4(r0, r1, r2, r3, addr) \
    asm volatile("ldmatrix.sync.aligned.m8n8.x4.shared.b16 {%0,%1,%2,%3}, [%4];" \
                 : "=r"(r0), "=r"(r1), "=r"(r2), "=r"(r3) : "r"(addr))
#define LDMATRIX_X2(r0, r1, addr) \
    asm volatile("ldmatrix.sync.aligned.m8n8.x2.shared.b16 {%0,%1}, [%2];" \
                 : "=r"(r0), "=r"(r1) : "r"(addr))
#define MMA_BF16(d0, d1, d2, d3, a0, a1, a2, a3, b0, b1) \
    asm volatile("mma.sync.aligned.m16n8k16.row.col.f32.bf16.bf16.f32 " \
                 "{%0,%1,%2,%3}, {%4,%5,%6,%7}, {%8,%9}, {%0,%1,%2,%3};" \
                 : "+f"(d0), "+f"(d1), "+f"(d2), "+f"(d3) \
                 : "r"(a0), "r"(a1), "r"(a2), "r"(a3), "r"(b0), "r"(b1))

// ---------------------------------------------------------------------------
// K1: per-(b,n) inverse channel norm: 16 / max(||x[:,n]||, eps)
// ---------------------------------------------------------------------------
__global__ __launch_bounds__(256) void k_rnorm(const float* __restrict__ x) {
    int idx = blockIdx.x * 256 + threadIdx.x;   // b*NDIM + n
    int b = idx >> 12;
    int n = idx & (NDIM - 1);
    const float* xp = x + (size_t)b * CDIM * NDIM + n;
    float s = 0.f;
    #pragma unroll 8
    for (int c = 0; c < CDIM; c++) {
        float v = xp[(size_t)c * NDIM];
        s += v * v;
    }
    g_rnorm[idx] = 16.0f / fmaxf(sqrtf(s), EPSN);
}

// ---------------------------------------------------------------------------
// K1b: W*g -> bf16 hi/lo, [o][k] row-major
// ---------------------------------------------------------------------------
__global__ __launch_bounds__(256) void k_wsplit(const float* __restrict__ wqkv,
                                                const float* __restrict__ gch) {
    int e = blockIdx.x * 256 + threadIdx.x;     // 0 .. 384*256-1
    int k = e & 255;
    float w = wqkv[e] * gch[k];
    __nv_bfloat16 hi = __float2bfloat16(w);
    __nv_bfloat16 lo = __float2bfloat16(w - __bfloat162float(hi));
    g_wh[e] = hi;
    g_wl[e] = lo;
}

// ---------------------------------------------------------------------------
// K1d: w_out -> bf16 hi/lo, [o][k] row-major (256x128)
// ---------------------------------------------------------------------------
__global__ __launch_bounds__(256) void k_osplit(const float* __restrict__ wout) {
    int e = blockIdx.x * 256 + threadIdx.x;     // 0 .. 256*128-1
    float w = wout[e];
    __nv_bfloat16 hi = __float2bfloat16(w);
    __nv_bfloat16 lo = __float2bfloat16(w - __bfloat162float(hi));
    g_woh[e] = hi;
    g_wol[e] = lo;
}

// ---------------------------------------------------------------------------
// K1c: x*rnorm -> transposed bf16 hi/lo [b][n][c] (k-contiguous)
// ---------------------------------------------------------------------------
__global__ __launch_bounds__(256) void k_xsplit(const float* __restrict__ x) {
    __shared__ float s[64][65];
    int n0 = blockIdx.x * 64;
    int c0 = blockIdx.y * 64;
    int b  = blockIdx.z;
    int tid = threadIdx.x;
    const float* xb = x + (size_t)b * CDIM * NDIM;

    #pragma unroll
    for (int idx = tid; idx < 1024; idx += 256) {
        int row = idx >> 4, ch = idx & 15;      // c-row, n-chunk
        float4 v = *(const float4*)(xb + (size_t)(c0 + row) * NDIM + n0 + ch * 4);
        s[row][ch * 4 + 0] = v.x;
        s[row][ch * 4 + 1] = v.y;
        s[row][ch * 4 + 2] = v.z;
        s[row][ch * 4 + 3] = v.w;
    }
    __syncthreads();

    #pragma unroll
    for (int idx = tid; idx < 2048; idx += 256) {
        int nr = idx >> 5, cp = idx & 31;       // out n-row, c-pair
        float rn = g_rnorm[b * NDIM + n0 + nr];
        float v0 = s[cp * 2 + 0][nr] * rn;
        float v1 = s[cp * 2 + 1][nr] * rn;
        __nv_bfloat16 h0 = __float2bfloat16(v0);
        __nv_bfloat16 h1 = __float2bfloat16(v1);
        __nv_bfloat16 l0 = __float2bfloat16(v0 - __bfloat162float(h0));
        __nv_bfloat16 l1 = __float2bfloat16(v1 - __bfloat162float(h1));
        uint32_t hp = (uint32_t)*(uint16_t*)&h0 | ((uint32_t)*(uint16_t*)&h1 << 16);
        uint32_t lp = (uint32_t)*(uint16_t*)&l0 | ((uint32_t)*(uint16_t*)&l1 << 16);
        size_t o = ((size_t)b * NDIM + n0 + nr) * CDIM + c0 + cp * 2;
        *(uint32_t*)&g_xh[o] = hp;
        *(uint32_t*)&g_xl[o] = lp;
    }
}

// ---------------------------------------------------------------------------
// K2: QKV GEMM via mma.sync bf16 (split-bf16, 3 terms).
// ---------------------------------------------------------------------------
#define RS 80
#define T_AH 0
#define T_AL 10240
#define T_BH 20480
#define T_BL 30720
#define STG  40960

__global__ __launch_bounds__(256) void k_qkv_mma() {
    extern __shared__ char smem[];
    uint32_t sb = smem_u32(smem);
    int tid = threadIdx.x;
    int lane = tid & 31, wid = tid >> 5;
    int wm = wid & 1, wn = wid >> 1;
    int m0 = blockIdx.x * 128;
    int n0 = blockIdx.y * 128;
    int b  = blockIdx.z;

    const __nv_bfloat16* xhb = g_xh + (size_t)b * NDIM * CDIM;
    const __nv_bfloat16* xlb = g_xl + (size_t)b * NDIM * CDIM;

    float acc[4][4][4];
    #pragma unroll
    for (int i = 0; i < 4; i++)
        #pragma unroll
        for (int j = 0; j < 4; j++)
            #pragma unroll
            for (int r = 0; r < 4; r++) acc[i][j][r] = 0.f;

    auto issue_stage = [&](int s) {
        int k0 = s * 32;
        uint32_t dst_base = sb + (s & 1) * STG;
        #pragma unroll
        for (int t = 0; t < 8; t++) {
            int idx = tid + t * 256;
            int tile = idx >> 9;
            int i = idx & 511;
            int row = i >> 2, pos = i & 3;
            uint32_t daddr = dst_base + tile * 10240 + row * RS + pos * 16;
            const __nv_bfloat16* src;
            if (tile == 0)      src = g_wh + (size_t)(m0 + row) * CDIM + k0 + pos * 8;
            else if (tile == 1) src = g_wl + (size_t)(m0 + row) * CDIM + k0 + pos * 8;
            else if (tile == 2) src = xhb + (size_t)(n0 + row) * CDIM + k0 + pos * 8;
            else                src = xlb + (size_t)(n0 + row) * CDIM + k0 + pos * 8;
            CP_ASYNC16(daddr, src);
        }
        CP_COMMIT();
    };

    issue_stage(0);
    for (int s = 0; s < 8; s++) {
        if (s + 1 < 8) {
            issue_stage(s + 1);
            CP_WAIT(1);
        } else {
            CP_WAIT(0);
        }
        __syncthreads();
        uint32_t buf = sb + (s & 1) * STG;

        #pragma unroll
        for (int ks = 0; ks < 2; ks++) {
            uint32_t ah[4][4], al[4][4], bh[4][2], bl[4][2];
            int akoff = (ks * 16 + (lane >> 4) * 8) * 2;
            int arow = (lane & 15);
            #pragma unroll
            for (int mi = 0; mi < 4; mi++) {
                int rb = wm * 64 + mi * 16 + arow;
                uint32_t ad = buf + T_AH + rb * RS + akoff;
                LDMATRIX_X4(ah[mi][0], ah[mi][1], ah[mi][2], ah[mi][3], ad);
                uint32_t ad2 = buf + T_AL + rb * RS + akoff;
                LDMATRIX_X4(al[mi][0], al[mi][1], al[mi][2], al[mi][3], ad2);
            }
            int l = lane & 15;
            int bkoff = (ks * 16 + (l >> 3) * 8) * 2;
            int brow = l & 7;
            #pragma unroll
            for (int ni = 0; ni < 4; ni++) {
                int rb = wn * 32 + ni * 8 + brow;
                uint32_t bd = buf + T_BH + rb * RS + bkoff;
                LDMATRIX_X2(bh[ni][0], bh[ni][1], bd);
                uint32_t bd2 = buf + T_BL + rb * RS + bkoff;
                LDMATRIX_X2(bl[ni][0], bl[ni][1], bd2);
            }
            #pragma unroll
            for (int mi = 0; mi < 4; mi++)
                #pragma unroll
                for (int ni = 0; ni < 4; ni++)
                    MMA_BF16(acc[mi][ni][0], acc[mi][ni][1], acc[mi][ni][2], acc[mi][ni][3],
                             ah[mi][0], ah[mi][1], ah[mi][2], ah[mi][3], bh[ni][0], bh[ni][1]);
            #pragma unroll
            for (int mi = 0; mi < 4; mi++)
                #pragma unroll
                for (int ni = 0; ni < 4; ni++)
                    MMA_BF16(acc[mi][ni][0], acc[mi][ni][1], acc[mi][ni][2], acc[mi][ni][3],
                             ah[mi][0], ah[mi][1], ah[mi][2], ah[mi][3], bl[ni][0], bl[ni][1]);
            #pragma unroll
            for (int mi = 0; mi < 4; mi++)
                #pragma unroll
                for (int ni = 0; ni < 4; ni++)
                    MMA_BF16(acc[mi][ni][0], acc[mi][ni][1], acc[mi][ni][2], acc[mi][ni][3],
                             al[mi][0], al[mi][1], al[mi][2], al[mi][3], bh[ni][0], bh[ni][1]);
        }
        __syncthreads();
    }

    float* outp = g_qkv + (size_t)b * QKVROWS * NDIM;
    int tr = lane >> 2, tc = (lane & 3) * 2;
    #pragma unroll
    for (int mi = 0; mi < 4; mi++) {
        #pragma unroll
        for (int ni = 0; ni < 4; ni++) {
            int o0 = m0 + wm * 64 + mi * 16 + tr;
            int nn = n0 + wn * 32 + ni * 8 + tc;
            float2 v0 = make_float2(acc[mi][ni][0], acc[mi][ni][1]);
            float2 v1 = make_float2(acc[mi][ni][2], acc[mi][ni][3]);
            *(float2*)(outp + (size_t)o0 * NDIM + nn)       = v0;
            *(float2*)(outp + (size_t)(o0 + 8) * NDIM + nn) = v1;
        }
    }
}

// ---------------------------------------------------------------------------
// K3a: per-(b,h,d) max over n (including 4 memory tokens)
// ---------------------------------------------------------------------------
__global__ __launch_bounds__(128) void k_kmax(const float* __restrict__ memkv) {
    int row = blockIdx.x;             // b*128 + h*32 + d
    int b = row >> 7;
    int hd = row & 127;
    const float* kp = g_qkv + (size_t)b * QKVROWS * NDIM + (size_t)(HID + hd) * NDIM;
    float m = -INFINITY;
    for (int n = threadIdx.x; n < NDIM; n += 128) m = fmaxf(m, kp[n]);
    __shared__ float red[128];
    red[threadIdx.x] = m;
    __syncthreads();
    for (int s = 64; s > 0; s >>= 1) {
        if (threadIdx.x < s) red[threadIdx.x] = fmaxf(red[threadIdx.x], red[threadIdx.x + s]);
        __syncthreads();
    }
    if (threadIdx.x == 0) {
        float mm = red[0];
        #pragma unroll
        for (int j = 0; j < NMEM; j++) mm = fmaxf(mm, memkv[hd * NMEM + j]);
        g_kmax[row] = mm;
    }
}

// ---------------------------------------------------------------------------
// K3b (stage A): partial ctx over an n-chunk of 512, split 4-way in j.
// ---------------------------------------------------------------------------
__global__ __launch_bounds__(256) void k_ctx_part() {
    __shared__ float ks[32 * 129];
    __shared__ float vs[32 * 129];
    __shared__ float kml[32];
    int chunk = blockIdx.x;           // 0..7
    int bh = blockIdx.y;              // 0..63
    int b = bh >> 2, h = bh & 3;
    int tid = threadIdx.x;
    int jp = tid >> 6;                // 0..3 j-partition
    int tile = tid & 63;
    int d0 = (tile & 7) * 4;
    int e0 = (tile >> 3) * 4;

    const float* base = g_qkv + (size_t)b * QKVROWS * NDIM;
    const float* kp = base + (size_t)(HID + h * ADIM) * NDIM;
    const float* vp = base + (size_t)(2 * HID + h * ADIM) * NDIM;

    if (tid < 32) kml[tid] = g_kmax[b * 128 + h * 32 + tid];
    __syncthreads();

    float acc[4][4];
    #pragma unroll
    for (int i = 0; i < 4; i++)
        #pragma unroll
        for (int m = 0; m < 4; m++) acc[i][m] = 0.f;
    float zacc[4] = {0.f, 0.f, 0.f, 0.f};

    for (int st = 0; st < 4; st++) {
        int n0 = chunk * 512 + st * 128;
        __syncthreads();
        #pragma unroll
        for (int f = tid; f < 1024; f += 256) {
            int r = f >> 5, c4 = (f & 31) * 4;
            float km = kml[r];
            float4 kv = *(const float4*)(kp + (size_t)r * NDIM + n0 + c4);
            ks[r * 129 + c4 + 0] = expf(kv.x - km);
            ks[r * 129 + c4 + 1] = expf(kv.y - km);
            ks[r * 129 + c4 + 2] = expf(kv.z - km);
            ks[r * 129 + c4 + 3] = expf(kv.w - km);
            float4 vv = *(const float4*)(vp + (size_t)r * NDIM + n0 + c4);
            vs[r * 129 + c4 + 0] = vv.x;
            vs[r * 129 + c4 + 1] = vv.y;
            vs[r * 129 + c4 + 2] = vv.z;
            vs[r * 129 + c4 + 3] = vv.w;
        }
        __syncthreads();
        #pragma unroll 4
        for (int jj = 0; jj < 32; jj++) {
            int j = jp * 32 + jj;
            float kd[4], vv[4];
            #pragma unroll
            for (int i = 0; i < 4; i++) kd[i] = ks[(d0 + i) * 129 + j];
            #pragma unroll
            for (int m = 0; m < 4; m++) vv[m] = vs[(e0 + m) * 129 + j];
            #pragma unroll
            for (int i = 0; i < 4; i++)
                #pragma unroll
                for (int m = 0; m < 4; m++) acc[i][m] += kd[i] * vv[m];
            if (e0 == 0) {
                #pragma unroll
                for (int i = 0; i < 4; i++) zacc[i] += kd[i];
            }
        }
    }
    int pc = chunk * 4 + jp;
    float* pp = g_ctx_part + ((size_t)pc * 64 + bh) * 1024;
    #pragma unroll
    for (int i = 0; i < 4; i++) {
        float4 v = make_float4(acc[i][0], acc[i][1], acc[i][2], acc[i][3]);
        *(float4*)(pp + (d0 + i) * 32 + e0) = v;
    }
    if (e0 == 0) {
        float* zp = g_z_part + ((size_t)pc * 64 + bh) * 32;
        #pragma unroll
        for (int i = 0; i < 4; i++) zp[d0 + i] = zacc[i];
    }
}

// ---------------------------------------------------------------------------
// K3b (stage B): reduce 32 partials, add memory tokens, fold SCALE / Z.
// ---------------------------------------------------------------------------
__global__ __launch_bounds__(1024) void k_ctx_reduce(const float* __restrict__ memkv) {
    __shared__ float zs[32];
    int bh = blockIdx.x;
    int b = bh >> 2, h = bh & 3;
    int tid = threadIdx.x;
    int d = tid >> 5, e = tid & 31;

    float acc = 0.f;
    #pragma unroll 8
    for (int c = 0; c < 32; c++)
        acc += g_ctx_part[((size_t)c * 64 + bh) * 1024 + tid];

    float km = g_kmax[b * 128 + h * 32 + d];
    const float* mk = memkv + h * 128 + d * NMEM;
    const float* mv = memkv + 512 + h * 128 + e * NMEM;
    float zmem = 0.f;
    #pragma unroll
    for (int j = 0; j < NMEM; j++) {
        float ek = expf(mk[j] - km);
        acc += ek * mv[j];
        zmem += ek;
    }
    if (e == 0) {
        float z = zmem;
        #pragma unroll 8
        for (int c = 0; c < 32; c++)
            z += g_z_part[((size_t)c * 64 + bh) * 32 + d];
        zs[d] = z;
    }
    __syncthreads();
    g_ctx[(size_t)bh * 1024 + tid] = acc * SCALE / zs[d];
}

// ---------------------------------------------------------------------------
// K4: fused epilogue with tensor-core out-projection.
// Block: (128-col n-tile, batch), 256 threads / 8 warps (4m x 2n).
// smem: qs fp32[128][128] | cs[4096] | osh/osl bf16[128][136] | W stages
// ---------------------------------------------------------------------------
#define QS_OFF   0
#define CS_OFF   65536
#define OSH_OFF  81920
#define OSL_OFF  116736
#define WST_OFF  151552
#define WSTG     24576
#define FIN_SMEM 200704

__global__ __launch_bounds__(256) void k_final_mma(const float* __restrict__ b_out,
                                                   const float* __restrict__ gout,
                                                   float* __restrict__ out) {
    extern __shared__ char smem[];
    uint32_t sb = smem_u32(smem);
    float* qs = (float*)(smem + QS_OFF);
    float* cs = (float*)(smem + CS_OFF);
    int tid = threadIdx.x;
    int lane = tid & 31, wid = tid >> 5;
    int wm = wid & 3, wn = wid >> 2;
    int b = blockIdx.y;
    int n0 = blockIdx.x * 128;
    const float* qp = g_qkv + (size_t)b * QKVROWS * NDIM;

    auto w_stage = [&](int kc) {
        uint32_t dst = sb + WST_OFF + (kc & 1) * WSTG;
        #pragma unroll
        for (int t = 0; t < 4; t++) {
            int idx = tid + t * 256;
            int sel = idx >> 9, i = idx & 511;
            int r = i >> 1, p = i & 1;
            const __nv_bfloat16* src = (sel ? g_wol : g_woh) + r * HID + kc * 16 + p * 8;
            CP_ASYNC16(dst + sel * 12288 + r * 48 + p * 16, src);
        }
        CP_COMMIT();
    };
    w_stage(0);
    w_stage(1);

    // load q tile [128][128] and ctx
    #pragma unroll
    for (int t = 0; t < 16; t++) {
        int idx = tid + t * 256;                 // 4096 float4
        int r = idx >> 5, c4 = (idx & 31) * 4;
        *(float4*)(qs + r * 128 + c4) = *(const float4*)(qp + (size_t)r * NDIM + n0 + c4);
    }
    #pragma unroll
    for (int t = 0; t < 4; t++) {
        int idx = tid + t * 256;                 // 1024 float4
        *(float4*)(cs + idx * 4) = *(const float4*)(g_ctx + b * 4096 + idx * 4);
    }
    __syncthreads();

    // softmax over d (per head-column) + os = ctx^T @ q, written as bf16 hi/lo [n][k]
    #pragma unroll
    for (int rep = 0; rep < 2; rep++) {
        int job = tid + rep * 256;
        int h = job >> 7, c = job & 127;
        const float* col = qs + (h * 32) * 128 + c;
        float qreg[32];
        float mx = -INFINITY;
        #pragma unroll
        for (int d = 0; d < 32; d++) { qreg[d] = col[d * 128]; mx = fmaxf(mx, qreg[d]); }
        float s = 0.f;
        #pragma unroll
        for (int d = 0; d < 32; d++) { qreg[d] = expf(qreg[d] - mx); s += qreg[d]; }
        float inv = 1.f / s;
        #pragma unroll
        for (int d = 0; d < 32; d++) qreg[d] *= inv;
        const float* ch = cs + h * 1024;
        #pragma unroll
        for (int e = 0; e < 32; e += 2) {
            float a0 = 0.f, a1 = 0.f;
            #pragma unroll
            for (int d = 0; d < 32; d++) {
                a0 += ch[d * 32 + e]     * qreg[d];
                a1 += ch[d * 32 + e + 1] * qreg[d];
            }
            __nv_bfloat16 h0 = __float2bfloat16(a0);
            __nv_bfloat16 h1 = __float2bfloat16(a1);
            __nv_bfloat16 l0 = __float2bfloat16(a0 - __bfloat162float(h0));
            __nv_bfloat16 l1 = __float2bfloat16(a1 - __bfloat162float(h1));
            uint32_t hp = (uint32_t)*(uint16_t*)&h0 | ((uint32_t)*(uint16_t*)&h1 << 16);
            uint32_t lp = (uint32_t)*(uint16_t*)&l0 | ((uint32_t)*(uint16_t*)&l1 << 16);
            uint32_t off = (uint32_t)c * 272 + (h * 32 + e) * 2;
            *(uint32_t*)(smem + OSH_OFF + off) = hp;
            *(uint32_t*)(smem + OSL_OFF + off) = lp;
        }
    }
    __syncthreads();

    // GEMM: out[256][128] = w_out(256x128) @ os(128x128), 3-term split bf16
    float acc[4][8][4];
    #pragma unroll
    for (int i = 0; i < 4; i++)
        #pragma unroll
        for (int j = 0; j < 8; j++)
            #pragma unroll
            for (int r = 0; r < 4; r++) acc[i][j][r] = 0.f;

    for (int kc = 0; kc < 8; kc++) {
        if (kc < 7) { CP_WAIT(1); } else { CP_WAIT(0); }
        __syncthreads();
        uint32_t wbuf = sb + WST_OFF + (kc & 1) * WSTG;

        uint32_t bh[8][2], bl[8][2];
        int l = lane & 15;
        uint32_t bko = (uint32_t)(kc * 32 + (l >> 3) * 16);
        #pragma unroll
        for (int ni = 0; ni < 8; ni++) {
            uint32_t rb = wn * 64 + ni * 8 + (l & 7);
            uint32_t boff = rb * 272 + bko;
            LDMATRIX_X2(bh[ni][0], bh[ni][1], sb + OSH_OFF + boff);
            LDMATRIX_X2(bl[ni][0], bl[ni][1], sb + OSL_OFF + boff);
        }
        uint32_t ako = (uint32_t)((lane >> 4) * 16);
        #pragma unroll
        for (int mi = 0; mi < 4; mi++) {
            uint32_t ra = wm * 64 + mi * 16 + (lane & 15);
            uint32_t ah[4], al[4];
            LDMATRIX_X4(ah[0], ah[1], ah[2], ah[3], wbuf + ra * 48 + ako);
            LDMATRIX_X4(al[0], al[1], al[2], al[3], wbuf + 12288 + ra * 48 + ako);
            #pragma unroll
            for (int ni = 0; ni < 8; ni++) {
                MMA_BF16(acc[mi][ni][0], acc[mi][ni][1], acc[mi][ni][2], acc[mi][ni][3],
                         ah[0], ah[1], ah[2], ah[3], bh[ni][0], bh[ni][1]);
                MMA_BF16(acc[mi][ni][0], acc[mi][ni][1], acc[mi][ni][2], acc[mi][ni][3],
                         ah[0], ah[1], ah[2], ah[3], bl[ni][0], bl[ni][1]);
                MMA_BF16(acc[mi][ni][0], acc[mi][ni][1], acc[mi][ni][2], acc[mi][ni][3],
                         al[0], al[1], al[2], al[3], bh[ni][0], bh[ni][1]);
            }
        }
        __syncthreads();
        if (kc + 2 < 8) w_stage(kc + 2);
    }

    // bias, per-column sum of squares, RMSNorm, write
    int tr = lane >> 2, tc2 = (lane & 3) * 2;
    float bo[4][2], go[4][2];
    #pragma unroll
    for (int mi = 0; mi < 4; mi++) {
        int o = wm * 64 + mi * 16 + tr;
        bo[mi][0] = b_out[o];     bo[mi][1] = b_out[o + 8];
        go[mi][0] = gout[o];      go[mi][1] = gout[o + 8];
    }
    float* red = cs;                  // reuse ctx region [128 cols][32 rowparts]
    #pragma unroll
    for (int ni = 0; ni < 8; ni++) {
        float s0 = 0.f, s1 = 0.f;
        #pragma unroll
        for (int mi = 0; mi < 4; mi++) {
            float v0 = acc[mi][ni][0] + bo[mi][0];
            float v1 = acc[mi][ni][1] + bo[mi][0];
            float v2 = acc[mi][ni][2] + bo[mi][1];
            float v3 = acc[mi][ni][3] + bo[mi][1];
            acc[mi][ni][0] = v0; acc[mi][ni][1] = v1;
            acc[mi][ni][2] = v2; acc[mi][ni][3] = v3;
            s0 += v0 * v0 + v2 * v2;
            s1 += v1 * v1 + v3 * v3;
        }
        int col = wn * 64 + ni * 8 + tc2;
        int rp = wm * 8 + tr;
        red[col * 32 + rp]       = s0;
        red[(col + 1) * 32 + rp] = s1;
    }
    __syncthreads();
    float* colsc = qs;                // reuse q region
    if (tid < 128) {
        float s = 0.f;
        #pragma unroll 8
        for (int t = 0; t < 32; t++) s += red[tid * 32 + t];
        colsc[tid] = 16.0f / fmaxf(sqrtf(s), EPSN);
    }
    __syncthreads();

    float* ob = out + (size_t)b * CDIM * NDIM;
    #pragma unroll
    for (int mi = 0; mi < 4; mi++) {
        int o0 = wm * 64 + mi * 16 + tr;
        #pragma unroll
        for (int ni = 0; ni < 8; ni++) {
            int col = wn * 64 + ni * 8 + tc2;
            float sc0 = colsc[col], sc1 = colsc[col + 1];
            float2 v0 = make_float2(acc[mi][ni][0] * sc0 * go[mi][0],
                                    acc[mi][ni][1] * sc1 * go[mi][0]);
            float2 v1 = make_float2(acc[mi][ni][2] * sc0 * go[mi][1],
                                    acc[mi][ni][3] * sc1 * go[mi][1]);
            *(float2*)(ob + (size_t)o0 * NDIM + n0 + col)       = v0;
            *(float2*)(ob + (size_t)(o0 + 8) * NDIM + n0 + col) = v1;
        }
    }
}

// ---------------------------------------------------------------------------
extern "C" void kernel_launch(void* const* d_in, const int* in_sizes, int n_in,
                              void* d_out, int out_size) {
    const float* x      = (const float*)d_in[0];
    const float* norm_g = (const float*)d_in[1];
    const float* w_qkv  = (const float*)d_in[2];
    const float* mem_kv = (const float*)d_in[3];
    const float* w_out  = (const float*)d_in[4];
    const float* b_out  = (const float*)d_in[5];
    const float* out_g  = (const float*)d_in[6];
    float* out = (float*)d_out;

    k_rnorm<<<(BATCH * NDIM) / 256, 256>>>(x);
    k_wsplit<<<(QKVROWS * CDIM) / 256, 256>>>(w_qkv, norm_g);
    k_osplit<<<(CDIM * HID) / 256, 256>>>(w_out);

    dim3 gx(NDIM / 64, CDIM / 64, BATCH);
    k_xsplit<<<gx, 256>>>(x);

    cudaFuncSetAttribute(k_qkv_mma, cudaFuncAttributeMaxDynamicSharedMemorySize, 2 * STG);
    dim3 g2(QKVROWS / 128, NDIM / 128, BATCH);
    k_qkv_mma<<<g2, 256, 2 * STG>>>();

    k_kmax<<<BATCH * HEADS * ADIM, 128>>>(mem_kv);

    dim3 g3(8, 64);
    k_ctx_part<<<g3, 256>>>();
    k_ctx_reduce<<<BATCH * HEADS, 1024>>>(mem_kv);

    cudaFuncSetAttribute(k_final_mma, cudaFuncAttributeMaxDynamicSharedMemorySize, FIN_SMEM);
    dim3 g4(NDIM / 128, BATCH);
    k_final_mma<<<g4, 256, FIN_SMEM>>>(b_out, out_g, out);
}

// round 8
// speedup vs baseline: 2.3760x; 1.0687x over previous
#include <cuda_runtime.h>
#include <cuda_bf16.h>
#include <math.h>
#include <stdint.h>

// Problem constants
#define BATCH 16
#define CDIM 256
#define NDIM 4096          // 64*64 spatial
#define HEADS 4
#define ADIM 32
#define HID 128
#define QKVROWS 384        // 3*HID
#define NMEM 4
#define SCALE 0.17677669529663687f   // 32^-0.5
#define EPSN 1e-12f
#define NCHUNK 16          // ctx n-chunks
#define NPART  64          // NCHUNK*4 partials

// Scratch (device globals: allocation-free per harness rules)
__device__ float g_qkv[(size_t)BATCH * QKVROWS * NDIM]; // ~100MB
__device__ float g_kmax[BATCH * HEADS * ADIM];
__device__ float g_ctx[BATCH * HEADS * ADIM * ADIM];    // already * SCALE / Z
__device__ float g_ctx_part[(size_t)NPART * 64 * 1024]; // 16MB partials
__device__ float g_z_part[NPART * 64 * 32];
// Pre-split bf16 operands (k-contiguous rows)
__device__ __nv_bfloat16 g_wh[QKVROWS * CDIM];
__device__ __nv_bfloat16 g_wl[QKVROWS * CDIM];
__device__ __nv_bfloat16 g_xh[(size_t)BATCH * NDIM * CDIM];  // [b][n][c]
__device__ __nv_bfloat16 g_xl[(size_t)BATCH * NDIM * CDIM];
// Pre-split w_out (256 x 128)
__device__ __nv_bfloat16 g_woh[CDIM * HID];
__device__ __nv_bfloat16 g_wol[CDIM * HID];

// ---------------------------------------------------------------------------
__device__ __forceinline__ uint32_t smem_u32(const void* p) {
    uint32_t a;
    asm("{ .reg .u64 t; cvta.to.shared.u64 t, %1; cvt.u32.u64 %0, t; }" : "=r"(a) : "l"(p));
    return a;
}
#define CP_ASYNC16(saddr, gaddr) \
    asm volatile("cp.async.cg.shared.global [%0], [%1], 16;" :: "r"(saddr), "l"(gaddr) : "memory")
#define CP_COMMIT() asm volatile("cp.async.commit_group;" ::: "memory")
#define CP_WAIT(n)  asm volatile("cp.async.wait_group %0;" :: "n"(n) : "memory")

#define LDMATRIX_X4(r0, r1, r2, r3, addr) \
    asm volatile("ldmatrix.sync.aligned.m8n8.x4.shared.b16 {%0,%1,%2,%3}, [%4];" \
                 : "=r"(r0), "=r"(r1), "=r"(r2), "=r"(r3) : "r"(addr))
#define LDMATRIX_X2(r0, r1, addr) \
    asm volatile("ldmatrix.sync.aligned.m8n8.x2.shared.b16 {%0,%1}, [%2];" \
                 : "=r"(r0), "=r"(r1) : "r"(addr))
#define MMA_BF16(d0, d1, d2, d3, a0, a1, a2, a3, b0, b1) \
    asm volatile("mma.sync.aligned.m16n8k16.row.col.f32.bf16.bf16.f32 " \
                 "{%0,%1,%2,%3}, {%4,%5,%6,%7}, {%8,%9}, {%0,%1,%2,%3};" \
                 : "+f"(d0), "+f"(d1), "+f"(d2), "+f"(d3) \
                 : "r"(a0), "r"(a1), "r"(a2), "r"(a3), "r"(b0), "r"(b1))

// Deterministic float atomic max (int/uint ordering trick)
__device__ __forceinline__ void atomicMaxF(float* addr, float v) {
    if (v >= 0.f) atomicMax((int*)addr, __float_as_int(v));
    else          atomicMin((unsigned int*)addr, __float_as_uint(v));
}

// ---------------------------------------------------------------------------
// K0: seed g_kmax with memory-token maxima (k_qkv epilogue atomicMax's the rest)
// ---------------------------------------------------------------------------
__global__ __launch_bounds__(256) void k_kinit(const float* __restrict__ memkv) {
    int idx = blockIdx.x * 256 + threadIdx.x;   // b*128 + hd
    int hd = idx & 127;
    float mm = -INFINITY;
    #pragma unroll
    for (int j = 0; j < NMEM; j++) mm = fmaxf(mm, memkv[hd * NMEM + j]);
    g_kmax[idx] = mm;
}

// ---------------------------------------------------------------------------
// K1b: W*g -> bf16 hi/lo, [o][k] row-major
// ---------------------------------------------------------------------------
__global__ __launch_bounds__(256) void k_wsplit(const float* __restrict__ wqkv,
                                                const float* __restrict__ gch) {
    int e = blockIdx.x * 256 + threadIdx.x;
    int k = e & 255;
    float w = wqkv[e] * gch[k];
    __nv_bfloat16 hi = __float2bfloat16(w);
    __nv_bfloat16 lo = __float2bfloat16(w - __bfloat162float(hi));
    g_wh[e] = hi;
    g_wl[e] = lo;
}

// ---------------------------------------------------------------------------
// K1d: w_out -> bf16 hi/lo, [o][k] row-major (256x128)
// ---------------------------------------------------------------------------
__global__ __launch_bounds__(256) void k_osplit(const float* __restrict__ wout) {
    int e = blockIdx.x * 256 + threadIdx.x;
    float w = wout[e];
    __nv_bfloat16 hi = __float2bfloat16(w);
    __nv_bfloat16 lo = __float2bfloat16(w - __bfloat162float(hi));
    g_woh[e] = hi;
    g_wol[e] = lo;
}

// ---------------------------------------------------------------------------
// K1: fused rnorm + transpose + bf16 split.
// Block = (64-n tile, batch). Loads x[256 c][64 n], computes channel norm,
// writes bf16 hi/lo [b][n][c]. smem rows padded to 67 floats (2-way max).
// ---------------------------------------------------------------------------
#define XP_PAD 67
#define XP_SMEM ((256 * XP_PAD + 4 * 64 + 64) * 4)

__global__ __launch_bounds__(256) void k_xprep(const float* __restrict__ x) {
    extern __shared__ float xs[];
    float* red = xs + 256 * XP_PAD;   // [4][64]
    float* rns = red + 256;           // [64]
    int n0 = blockIdx.x * 64;
    int b  = blockIdx.y;
    int tid = threadIdx.x;
    const float* xb = x + (size_t)b * CDIM * NDIM;

    // load x[256][64] (coalesced rows)
    #pragma unroll
    for (int t = 0; t < 16; t++) {
        int idx = tid + t * 256;      // 0..4095
        int c = idx >> 4, nch = idx & 15;
        float4 v = *(const float4*)(xb + (size_t)c * NDIM + n0 + nch * 4);
        float* row = xs + c * XP_PAD + nch * 4;
        row[0] = v.x; row[1] = v.y; row[2] = v.z; row[3] = v.w;
    }
    __syncthreads();

    // per-column sum of squares (4 partials of 64 channels)
    {
        int n = tid & 63, p = tid >> 6;
        const float* col = xs + (p * 64) * XP_PAD + n;
        float s = 0.f;
        #pragma unroll 16
        for (int i = 0; i < 64; i++) {
            float v = col[i * XP_PAD];
            s += v * v;
        }
        red[p * 64 + n] = s;
    }
    __syncthreads();
    if (tid < 64) {
        float s = red[tid] + red[64 + tid] + red[128 + tid] + red[192 + tid];
        rns[tid] = 16.0f / fmaxf(sqrtf(s), EPSN);
    }
    __syncthreads();

    // output: job = n*128 + cpair (coalesced global writes)
    #pragma unroll
    for (int t = 0; t < 32; t++) {
        int job = tid + t * 256;      // 0..8191
        int cp = job & 127, n = job >> 7;
        float rn = rns[n];
        float v0 = xs[(2 * cp + 0) * XP_PAD + n] * rn;
        float v1 = xs[(2 * cp + 1) * XP_PAD + n] * rn;
        __nv_bfloat16 h0 = __float2bfloat16(v0);
        __nv_bfloat16 h1 = __float2bfloat16(v1);
        __nv_bfloat16 l0 = __float2bfloat16(v0 - __bfloat162float(h0));
        __nv_bfloat16 l1 = __float2bfloat16(v1 - __bfloat162float(h1));
        uint32_t hp = (uint32_t)*(uint16_t*)&h0 | ((uint32_t)*(uint16_t*)&h1 << 16);
        uint32_t lp = (uint32_t)*(uint16_t*)&l0 | ((uint32_t)*(uint16_t*)&l1 << 16);
        size_t o = ((size_t)b * NDIM + n0 + n) * CDIM + cp * 2;
        *(uint32_t*)&g_xh[o] = hp;
        *(uint32_t*)&g_xl[o] = lp;
    }
}

// ---------------------------------------------------------------------------
// K2: QKV GEMM via mma.sync bf16 (split-bf16, 3 terms).
// Epilogue also atomicMax's K rows into g_kmax (blockIdx.x == 1).
// ---------------------------------------------------------------------------
#define RS 80
#define T_AH 0
#define T_AL 10240
#define T_BH 20480
#define T_BL 30720
#define STG  40960

__global__ __launch_bounds__(256) void k_qkv_mma() {
    extern __shared__ char smem[];
    uint32_t sb = smem_u32(smem);
    int tid = threadIdx.x;
    int lane = tid & 31, wid = tid >> 5;
    int wm = wid & 1, wn = wid >> 1;
    int m0 = blockIdx.x * 128;
    int n0 = blockIdx.y * 128;
    int b  = blockIdx.z;

    const __nv_bfloat16* xhb = g_xh + (size_t)b * NDIM * CDIM;
    const __nv_bfloat16* xlb = g_xl + (size_t)b * NDIM * CDIM;

    float acc[4][4][4];
    #pragma unroll
    for (int i = 0; i < 4; i++)
        #pragma unroll
        for (int j = 0; j < 4; j++)
            #pragma unroll
            for (int r = 0; r < 4; r++) acc[i][j][r] = 0.f;

    auto issue_stage = [&](int s) {
        int k0 = s * 32;
        uint32_t dst_base = sb + (s & 1) * STG;
        #pragma unroll
        for (int t = 0; t < 8; t++) {
            int idx = tid + t * 256;
            int tile = idx >> 9;
            int i = idx & 511;
            int row = i >> 2, pos = i & 3;
            uint32_t daddr = dst_base + tile * 10240 + row * RS + pos * 16;
            const __nv_bfloat16* src;
            if (tile == 0)      src = g_wh + (size_t)(m0 + row) * CDIM + k0 + pos * 8;
            else if (tile == 1) src = g_wl + (size_t)(m0 + row) * CDIM + k0 + pos * 8;
            else if (tile == 2) src = xhb + (size_t)(n0 + row) * CDIM + k0 + pos * 8;
            else                src = xlb + (size_t)(n0 + row) * CDIM + k0 + pos * 8;
            CP_ASYNC16(daddr, src);
        }
        CP_COMMIT();
    };

    issue_stage(0);
    for (int s = 0; s < 8; s++) {
        if (s + 1 < 8) {
            issue_stage(s + 1);
            CP_WAIT(1);
        } else {
            CP_WAIT(0);
        }
        __syncthreads();
        uint32_t buf = sb + (s & 1) * STG;

        #pragma unroll
        for (int ks = 0; ks < 2; ks++) {
            uint32_t ah[4][4], al[4][4], bh[4][2], bl[4][2];
            int akoff = (ks * 16 + (lane >> 4) * 8) * 2;
            int arow = (lane & 15);
            #pragma unroll
            for (int mi = 0; mi < 4; mi++) {
                int rb = wm * 64 + mi * 16 + arow;
                uint32_t ad = buf + T_AH + rb * RS + akoff;
                LDMATRIX_X4(ah[mi][0], ah[mi][1], ah[mi][2], ah[mi][3], ad);
                uint32_t ad2 = buf + T_AL + rb * RS + akoff;
                LDMATRIX_X4(al[mi][0], al[mi][1], al[mi][2], al[mi][3], ad2);
            }
            int l = lane & 15;
            int bkoff = (ks * 16 + (l >> 3) * 8) * 2;
            int brow = l & 7;
            #pragma unroll
            for (int ni = 0; ni < 4; ni++) {
                int rb = wn * 32 + ni * 8 + brow;
                uint32_t bd = buf + T_BH + rb * RS + bkoff;
                LDMATRIX_X2(bh[ni][0], bh[ni][1], bd);
                uint32_t bd2 = buf + T_BL + rb * RS + bkoff;
                LDMATRIX_X2(bl[ni][0], bl[ni][1], bd2);
            }
            #pragma unroll
            for (int mi = 0; mi < 4; mi++)
                #pragma unroll
                for (int ni = 0; ni < 4; ni++)
                    MMA_BF16(acc[mi][ni][0], acc[mi][ni][1], acc[mi][ni][2], acc[mi][ni][3],
                             ah[mi][0], ah[mi][1], ah[mi][2], ah[mi][3], bh[ni][0], bh[ni][1]);
            #pragma unroll
            for (int mi = 0; mi < 4; mi++)
                #pragma unroll
                for (int ni = 0; ni < 4; ni++)
                    MMA_BF16(acc[mi][ni][0], acc[mi][ni][1], acc[mi][ni][2], acc[mi][ni][3],
                             ah[mi][0], ah[mi][1], ah[mi][2], ah[mi][3], bl[ni][0], bl[ni][1]);
            #pragma unroll
            for (int mi = 0; mi < 4; mi++)
                #pragma unroll
                for (int ni = 0; ni < 4; ni++)
                    MMA_BF16(acc[mi][ni][0], acc[mi][ni][1], acc[mi][ni][2], acc[mi][ni][3],
                             al[mi][0], al[mi][1], al[mi][2], al[mi][3], bh[ni][0], bh[ni][1]);
        }
        __syncthreads();
    }

    float* outp = g_qkv + (size_t)b * QKVROWS * NDIM;
    int tr = lane >> 2, tc = (lane & 3) * 2;
    #pragma unroll
    for (int mi = 0; mi < 4; mi++) {
        #pragma unroll
        for (int ni = 0; ni < 4; ni++) {
            int o0 = m0 + wm * 64 + mi * 16 + tr;
            int nn = n0 + wn * 32 + ni * 8 + tc;
            float2 v0 = make_float2(acc[mi][ni][0], acc[mi][ni][1]);
            float2 v1 = make_float2(acc[mi][ni][2], acc[mi][ni][3]);
            *(float2*)(outp + (size_t)o0 * NDIM + nn)       = v0;
            *(float2*)(outp + (size_t)(o0 + 8) * NDIM + nn) = v1;
        }
    }

    // K-block: reduce row maxima and atomicMax into g_kmax
    if (blockIdx.x == 1) {
        #pragma unroll
        for (int mi = 0; mi < 4; mi++) {
            float mA = -INFINITY, mB = -INFINITY;
            #pragma unroll
            for (int ni = 0; ni < 4; ni++) {
                mA = fmaxf(mA, fmaxf(acc[mi][ni][0], acc[mi][ni][1]));
                mB = fmaxf(mB, fmaxf(acc[mi][ni][2], acc[mi][ni][3]));
            }
            // combine the 4 lanes sharing these rows (lane bits 0-1)
            mA = fmaxf(mA, __shfl_xor_sync(0xffffffffu, mA, 1));
            mA = fmaxf(mA, __shfl_xor_sync(0xffffffffu, mA, 2));
            mB = fmaxf(mB, __shfl_xor_sync(0xffffffffu, mB, 1));
            mB = fmaxf(mB, __shfl_xor_sync(0xffffffffu, mB, 2));
            if ((lane & 3) == 0) {
                int hd = wm * 64 + mi * 16 + tr;   // K row 0..127
                atomicMaxF(&g_kmax[b * 128 + hd], mA);
                atomicMaxF(&g_kmax[b * 128 + hd + 8], mB);
            }
        }
    }
}

// ---------------------------------------------------------------------------
// K3b (stage A): partial ctx over an n-chunk of 256, split 4-way in j.
// grid = (16 chunks, 64 bh), 256 threads.
// ---------------------------------------------------------------------------
__global__ __launch_bounds__(256) void k_ctx_part() {
    __shared__ float ks[32 * 129];
    __shared__ float vs[32 * 129];
    __shared__ float kml[32];
    int chunk = blockIdx.x;           // 0..15
    int bh = blockIdx.y;              // 0..63
    int b = bh >> 2, h = bh & 3;
    int tid = threadIdx.x;
    int jp = tid >> 6;                // 0..3 j-partition
    int tile = tid & 63;
    int d0 = (tile & 7) * 4;
    int e0 = (tile >> 3) * 4;

    const float* base = g_qkv + (size_t)b * QKVROWS * NDIM;
    const float* kp = base + (size_t)(HID + h * ADIM) * NDIM;
    const float* vp = base + (size_t)(2 * HID + h * ADIM) * NDIM;

    if (tid < 32) kml[tid] = g_kmax[b * 128 + h * 32 + tid];
    __syncthreads();

    float acc[4][4];
    #pragma unroll
    for (int i = 0; i < 4; i++)
        #pragma unroll
        for (int m = 0; m < 4; m++) acc[i][m] = 0.f;
    float zacc[4] = {0.f, 0.f, 0.f, 0.f};

    for (int st = 0; st < 2; st++) {
        int n0 = chunk * 256 + st * 128;
        __syncthreads();
        #pragma unroll
        for (int f = tid; f < 1024; f += 256) {
            int r = f >> 5, c4 = (f & 31) * 4;
            float km = kml[r];
            float4 kv = *(const float4*)(kp + (size_t)r * NDIM + n0 + c4);
            ks[r * 129 + c4 + 0] = expf(kv.x - km);
            ks[r * 129 + c4 + 1] = expf(kv.y - km);
            ks[r * 129 + c4 + 2] = expf(kv.z - km);
            ks[r * 129 + c4 + 3] = expf(kv.w - km);
            float4 vv = *(const float4*)(vp + (size_t)r * NDIM + n0 + c4);
            vs[r * 129 + c4 + 0] = vv.x;
            vs[r * 129 + c4 + 1] = vv.y;
            vs[r * 129 + c4 + 2] = vv.z;
            vs[r * 129 + c4 + 3] = vv.w;
        }
        __syncthreads();
        #pragma unroll 4
        for (int jj = 0; jj < 32; jj++) {
            int j = jp * 32 + jj;
            float kd[4], vv[4];
            #pragma unroll
            for (int i = 0; i < 4; i++) kd[i] = ks[(d0 + i) * 129 + j];
            #pragma unroll
            for (int m = 0; m < 4; m++) vv[m] = vs[(e0 + m) * 129 + j];
            #pragma unroll
            for (int i = 0; i < 4; i++)
                #pragma unroll
                for (int m = 0; m < 4; m++) acc[i][m] += kd[i] * vv[m];
            if (e0 == 0) {
                #pragma unroll
                for (int i = 0; i < 4; i++) zacc[i] += kd[i];
            }
        }
    }
    int pc = chunk * 4 + jp;          // 0..63
    float* pp = g_ctx_part + ((size_t)pc * 64 + bh) * 1024;
    #pragma unroll
    for (int i = 0; i < 4; i++) {
        float4 v = make_float4(acc[i][0], acc[i][1], acc[i][2], acc[i][3]);
        *(float4*)(pp + (d0 + i) * 32 + e0) = v;
    }
    if (e0 == 0) {
        float* zp = g_z_part + ((size_t)pc * 64 + bh) * 32;
        #pragma unroll
        for (int i = 0; i < 4; i++) zp[d0 + i] = zacc[i];
    }
}

// ---------------------------------------------------------------------------
// K3b (stage B): reduce NPART partials, add memory tokens, fold SCALE / Z.
// ---------------------------------------------------------------------------
__global__ __launch_bounds__(1024) void k_ctx_reduce(const float* __restrict__ memkv) {
    __shared__ float zs[32];
    int bh = blockIdx.x;
    int b = bh >> 2, h = bh & 3;
    int tid = threadIdx.x;
    int d = tid >> 5, e = tid & 31;

    float acc = 0.f;
    #pragma unroll 8
    for (int c = 0; c < NPART; c++)
        acc += g_ctx_part[((size_t)c * 64 + bh) * 1024 + tid];

    float km = g_kmax[b * 128 + h * 32 + d];
    const float* mk = memkv + h * 128 + d * NMEM;
    const float* mv = memkv + 512 + h * 128 + e * NMEM;
    float zmem = 0.f;
    #pragma unroll
    for (int j = 0; j < NMEM; j++) {
        float ek = expf(mk[j] - km);
        acc += ek * mv[j];
        zmem += ek;
    }
    if (e == 0) {
        float z = zmem;
        #pragma unroll 8
        for (int c = 0; c < NPART; c++)
            z += g_z_part[((size_t)c * 64 + bh) * 32 + d];
        zs[d] = z;
    }
    __syncthreads();
    g_ctx[(size_t)bh * 1024 + tid] = acc * SCALE / zs[d];
}

// ---------------------------------------------------------------------------
// K4: fused epilogue with tensor-core out-projection.
// ---------------------------------------------------------------------------
#define QS_OFF   0
#define CS_OFF   65536
#define OSH_OFF  81920
#define OSL_OFF  116736
#define WST_OFF  151552
#define WSTG     24576
#define FIN_SMEM 200704

__global__ __launch_bounds__(256) void k_final_mma(const float* __restrict__ b_out,
                                                   const float* __restrict__ gout,
                                                   float* __restrict__ out) {
    extern __shared__ char smem[];
    uint32_t sb = smem_u32(smem);
    float* qs = (float*)(smem + QS_OFF);
    float* cs = (float*)(smem + CS_OFF);
    int tid = threadIdx.x;
    int lane = tid & 31, wid = tid >> 5;
    int wm = wid & 3, wn = wid >> 2;
    int b = blockIdx.y;
    int n0 = blockIdx.x * 128;
    const float* qp = g_qkv + (size_t)b * QKVROWS * NDIM;

    auto w_stage = [&](int kc) {
        uint32_t dst = sb + WST_OFF + (kc & 1) * WSTG;
        #pragma unroll
        for (int t = 0; t < 4; t++) {
            int idx = tid + t * 256;
            int sel = idx >> 9, i = idx & 511;
            int r = i >> 1, p = i & 1;
            const __nv_bfloat16* src = (sel ? g_wol : g_woh) + r * HID + kc * 16 + p * 8;
            CP_ASYNC16(dst + sel * 12288 + r * 48 + p * 16, src);
        }
        CP_COMMIT();
    };
    w_stage(0);
    w_stage(1);

    #pragma unroll
    for (int t = 0; t < 16; t++) {
        int idx = tid + t * 256;
        int r = idx >> 5, c4 = (idx & 31) * 4;
        *(float4*)(qs + r * 128 + c4) = *(const float4*)(qp + (size_t)r * NDIM + n0 + c4);
    }
    #pragma unroll
    for (int t = 0; t < 4; t++) {
        int idx = tid + t * 256;
        *(float4*)(cs + idx * 4) = *(const float4*)(g_ctx + b * 4096 + idx * 4);
    }
    __syncthreads();

    #pragma unroll
    for (int rep = 0; rep < 2; rep++) {
        int job = tid + rep * 256;
        int h = job >> 7, c = job & 127;
        const float* col = qs + (h * 32) * 128 + c;
        float qreg[32];
        float mx = -INFINITY;
        #pragma unroll
        for (int d = 0; d < 32; d++) { qreg[d] = col[d * 128]; mx = fmaxf(mx, qreg[d]); }
        float s = 0.f;
        #pragma unroll
        for (int d = 0; d < 32; d++) { qreg[d] = expf(qreg[d] - mx); s += qreg[d]; }
        float inv = 1.f / s;
        #pragma unroll
        for (int d = 0; d < 32; d++) qreg[d] *= inv;
        const float* ch = cs + h * 1024;
        #pragma unroll
        for (int e = 0; e < 32; e += 2) {
            float a0 = 0.f, a1 = 0.f;
            #pragma unroll
            for (int d = 0; d < 32; d++) {
                a0 += ch[d * 32 + e]     * qreg[d];
                a1 += ch[d * 32 + e + 1] * qreg[d];
            }
            __nv_bfloat16 h0 = __float2bfloat16(a0);
            __nv_bfloat16 h1 = __float2bfloat16(a1);
            __nv_bfloat16 l0 = __float2bfloat16(a0 - __bfloat162float(h0));
            __nv_bfloat16 l1 = __float2bfloat16(a1 - __bfloat162float(h1));
            uint32_t hp = (uint32_t)*(uint16_t*)&h0 | ((uint32_t)*(uint16_t*)&h1 << 16);
            uint32_t lp = (uint32_t)*(uint16_t*)&l0 | ((uint32_t)*(uint16_t*)&l1 << 16);
            uint32_t off = (uint32_t)c * 272 + (h * 32 + e) * 2;
            *(uint32_t*)(smem + OSH_OFF + off) = hp;
            *(uint32_t*)(smem + OSL_OFF + off) = lp;
        }
    }
    __syncthreads();

    float acc[4][8][4];
    #pragma unroll
    for (int i = 0; i < 4; i++)
        #pragma unroll
        for (int j = 0; j < 8; j++)
            #pragma unroll
            for (int r = 0; r < 4; r++) acc[i][j][r] = 0.f;

    for (int kc = 0; kc < 8; kc++) {
        if (kc < 7) { CP_WAIT(1); } else { CP_WAIT(0); }
        __syncthreads();
        uint32_t wbuf = sb + WST_OFF + (kc & 1) * WSTG;

        uint32_t bh[8][2], bl[8][2];
        int l = lane & 15;
        uint32_t bko = (uint32_t)(kc * 32 + (l >> 3) * 16);
        #pragma unroll
        for (int ni = 0; ni < 8; ni++) {
            uint32_t rb = wn * 64 + ni * 8 + (l & 7);
            uint32_t boff = rb * 272 + bko;
            LDMATRIX_X2(bh[ni][0], bh[ni][1], sb + OSH_OFF + boff);
            LDMATRIX_X2(bl[ni][0], bl[ni][1], sb + OSL_OFF + boff);
        }
        uint32_t ako = (uint32_t)((lane >> 4) * 16);
        #pragma unroll
        for (int mi = 0; mi < 4; mi++) {
            uint32_t ra = wm * 64 + mi * 16 + (lane & 15);
            uint32_t ah[4], al[4];
            LDMATRIX_X4(ah[0], ah[1], ah[2], ah[3], wbuf + ra * 48 + ako);
            LDMATRIX_X4(al[0], al[1], al[2], al[3], wbuf + 12288 + ra * 48 + ako);
            #pragma unroll
            for (int ni = 0; ni < 8; ni++) {
                MMA_BF16(acc[mi][ni][0], acc[mi][ni][1], acc[mi][ni][2], acc[mi][ni][3],
                         ah[0], ah[1], ah[2], ah[3], bh[ni][0], bh[ni][1]);
                MMA_BF16(acc[mi][ni][0], acc[mi][ni][1], acc[mi][ni][2], acc[mi][ni][3],
                         ah[0], ah[1], ah[2], ah[3], bl[ni][0], bl[ni][1]);
                MMA_BF16(acc[mi][ni][0], acc[mi][ni][1], acc[mi][ni][2], acc[mi][ni][3],
                         al[0], al[1], al[2], al[3], bh[ni][0], bh[ni][1]);
            }
        }
        __syncthreads();
        if (kc + 2 < 8) w_stage(kc + 2);
    }

    int tr = lane >> 2, tc2 = (lane & 3) * 2;
    float bo[4][2], go[4][2];
    #pragma unroll
    for (int mi = 0; mi < 4; mi++) {
        int o = wm * 64 + mi * 16 + tr;
        bo[mi][0] = b_out[o];     bo[mi][1] = b_out[o + 8];
        go[mi][0] = gout[o];      go[mi][1] = gout[o + 8];
    }
    float* red = cs;
    #pragma unroll
    for (int ni = 0; ni < 8; ni++) {
        float s0 = 0.f, s1 = 0.f;
        #pragma unroll
        for (int mi = 0; mi < 4; mi++) {
            float v0 = acc[mi][ni][0] + bo[mi][0];
            float v1 = acc[mi][ni][1] + bo[mi][0];
            float v2 = acc[mi][ni][2] + bo[mi][1];
            float v3 = acc[mi][ni][3] + bo[mi][1];
            acc[mi][ni][0] = v0; acc[mi][ni][1] = v1;
            acc[mi][ni][2] = v2; acc[mi][ni][3] = v3;
            s0 += v0 * v0 + v2 * v2;
            s1 += v1 * v1 + v3 * v3;
        }
        int col = wn * 64 + ni * 8 + tc2;
        int rp = wm * 8 + tr;
        red[col * 32 + rp]       = s0;
        red[(col + 1) * 32 + rp] = s1;
    }
    __syncthreads();
    float* colsc = qs;
    if (tid < 128) {
        float s = 0.f;
        #pragma unroll 8
        for (int t = 0; t < 32; t++) s += red[tid * 32 + t];
        colsc[tid] = 16.0f / fmaxf(sqrtf(s), EPSN);
    }
    __syncthreads();

    float* ob = out + (size_t)b * CDIM * NDIM;
    #pragma unroll
    for (int mi = 0; mi < 4; mi++) {
        int o0 = wm * 64 + mi * 16 + tr;
        #pragma unroll
        for (int ni = 0; ni < 8; ni++) {
            int col = wn * 64 + ni * 8 + tc2;
            float sc0 = colsc[col], sc1 = colsc[col + 1];
            float2 v0 = make_float2(acc[mi][ni][0] * sc0 * go[mi][0],
                                    acc[mi][ni][1] * sc1 * go[mi][0]);
            float2 v1 = make_float2(acc[mi][ni][2] * sc0 * go[mi][1],
                                    acc[mi][ni][3] * sc1 * go[mi][1]);
            *(float2*)(ob + (size_t)o0 * NDIM + n0 + col)       = v0;
            *(float2*)(ob + (size_t)(o0 + 8) * NDIM + n0 + col) = v1;
        }
    }
}

// ---------------------------------------------------------------------------
extern "C" void kernel_launch(void* const* d_in, const int* in_sizes, int n_in,
                              void* d_out, int out_size) {
    const float* x      = (const float*)d_in[0];
    const float* norm_g = (const float*)d_in[1];
    const float* w_qkv  = (const float*)d_in[2];
    const float* mem_kv = (const float*)d_in[3];
    const float* w_out  = (const float*)d_in[4];
    const float* b_out  = (const float*)d_in[5];
    const float* out_g  = (const float*)d_in[6];
    float* out = (float*)d_out;

    k_kinit<<<(BATCH * 128) / 256, 256>>>(mem_kv);
    k_wsplit<<<(QKVROWS * CDIM) / 256, 256>>>(w_qkv, norm_g);
    k_osplit<<<(CDIM * HID) / 256, 256>>>(w_out);

    cudaFuncSetAttribute(k_xprep, cudaFuncAttributeMaxDynamicSharedMemorySize, XP_SMEM);
    dim3 gx(NDIM / 64, BATCH);
    k_xprep<<<gx, 256, XP_SMEM>>>(x);

    cudaFuncSetAttribute(k_qkv_mma, cudaFuncAttributeMaxDynamicSharedMemorySize, 2 * STG);
    dim3 g2(QKVROWS / 128, NDIM / 128, BATCH);
    k_qkv_mma<<<g2, 256, 2 * STG>>>();

    dim3 g3(NCHUNK, 64);
    k_ctx_part<<<g3, 256>>>();
    k_ctx_reduce<<<BATCH * HEADS, 1024>>>(mem_kv);

    cudaFuncSetAttribute(k_final_mma, cudaFuncAttributeMaxDynamicSharedMemorySize, FIN_SMEM);
    dim3 g4(NDIM / 128, BATCH);
    k_final_mma<<<g4, 256, FIN_SMEM>>>(b_out, out_g, out);
}